// round 10
// baseline (speedup 1.0000x reference)
#include <cuda_runtime.h>
#include <cuda_bf16.h>
#include <cstdint>

#define BSZ 8
#define CDIM 64
#define HDIM 128
#define WDIM 128
#define HID 128

// smem strides (bf16 elems)
#define LDA1 136   // K1 A: [c][w], 64 rows (ldmatrix pad)
#define LDB1 72    // K1 B: [o][c], 128 rows
#define LDS1 136   // K1 staging [o][w] bf16
#define LDA3 136   // K3 A: [o][w], 128 rows
#define LDB3 136   // K3 B: [c][o], 64 rows
#define LDP  132   // K3 fp32 staging [c][w]
#define LDK2 128   // K2 planes [h][w] bf16 — no pad needed (row/col access both conflict-free)

// ---- scratch (device globals; allocation-free) ----
__device__ __nv_bfloat16 g_xp[BSZ*HDIM*HID*WDIM];  // x_proj [b][h][o][w] bf16
__device__ __nv_bfloat16 g_hs[BSZ*HDIM*HID*WDIM];  // h_sum  [b][h][o][w] bf16
__device__ __align__(16) __nv_bfloat16 g_WinP[HID*LDB1];    // [o][c] padded
__device__ __align__(16) __nv_bfloat16 g_WoutP[CDIM*LDB3];  // [c][o] padded
__device__ float g_At[HID];

__device__ __forceinline__ uint32_t smem_u32(const void* p) {
    return (uint32_t)__cvta_generic_to_shared(p);
}

// ---- ldmatrix / mma.sync wrappers (sm_80-portable) ----
__device__ __forceinline__ void ldsm_x4_trans(uint32_t* r, uint32_t a) {
    asm volatile("ldmatrix.sync.aligned.m8n8.x4.trans.shared.b16 {%0,%1,%2,%3}, [%4];"
        : "=r"(r[0]), "=r"(r[1]), "=r"(r[2]), "=r"(r[3]) : "r"(a));
}
__device__ __forceinline__ void ldsm_x4(uint32_t* r, uint32_t a) {
    asm volatile("ldmatrix.sync.aligned.m8n8.x4.shared.b16 {%0,%1,%2,%3}, [%4];"
        : "=r"(r[0]), "=r"(r[1]), "=r"(r[2]), "=r"(r[3]) : "r"(a));
}
__device__ __forceinline__ void mma_bf16(float* d, const uint32_t* a, const uint32_t* b) {
    asm volatile("mma.sync.aligned.m16n8k16.row.col.f32.bf16.bf16.f32 "
        "{%0,%1,%2,%3}, {%4,%5,%6,%7}, {%8,%9}, {%0,%1,%2,%3};"
        : "+f"(d[0]), "+f"(d[1]), "+f"(d[2]), "+f"(d[3])
        : "r"(a[0]), "r"(a[1]), "r"(a[2]), "r"(a[3]), "r"(b[0]), "r"(b[1]));
}

// ---- bilinear prior 32->128, align_corners, clip ----
__device__ __forceinline__ float prior_at(const float* __restrict__ prior,
                                          int b, int h, int w) {
    const float s = 31.0f / 127.0f;
    float ys = h * s, xs = w * s;
    int y0 = (int)ys, x0 = (int)xs;
    int y1 = min(y0 + 1, 31), x1 = min(x0 + 1, 31);
    float wy = ys - (float)y0, wx = xs - (float)x0;
    const float* p = prior + b * 1024;
    float p00 = p[y0*32+x0], p01 = p[y0*32+x1];
    float p10 = p[y1*32+x0], p11 = p[y1*32+x1];
    float top = p00 + (p01 - p00) * wx;
    float bot = p10 + (p11 - p10) * wx;
    float v = top + (bot - top) * wy;
    return fminf(1.0f, fmaxf(-1.0f, v));
}

// ---- K0: weights -> padded bf16 layouts + tanh(A) ----
__global__ void k_setup(const float* __restrict__ Win,
                        const float* __restrict__ Wout,
                        const float* __restrict__ A) {
    int i = blockIdx.x * 256 + threadIdx.x;
    if (i < 8192) {
        int o = i >> 6, c = i & 63;
        g_WinP[o * LDB1 + c] = __float2bfloat16(Win[o * 64 + c]);
        int cc = i >> 7, oo = i & 127;
        g_WoutP[cc * LDB3 + oo] = __float2bfloat16(Wout[cc * 128 + oo]);
    }
    if (i < 128) g_At[i] = tanhf(A[i]);
}

// ---- K1: per-(b,h): x_proj = F_mod @ Win^T + b_in (HMMA) ----
// smem: sA [64c][136w] bf16 17408B @0 ; sB [128o][72c] bf16 18432B @17408
//       sPb [128o][136w] bf16 34816B overlays sA after MMA. total 35840B.
__global__ __launch_bounds__(256) void k1(
    const float* __restrict__ x, const float* __restrict__ prior,
    const float* __restrict__ b_in, const float* __restrict__ alpha_p)
{
    extern __shared__ __align__(16) char smch[];
    __nv_bfloat16* sA = (__nv_bfloat16*)smch;
    __nv_bfloat16* sB = (__nv_bfloat16*)(smch + 17408);
    __nv_bfloat16* sPb = (__nv_bfloat16*)smch;
    __shared__ float s_pr[128], s_bin[128];

    const int t = threadIdx.x;
    const int wid = t >> 5, lid = t & 31;
    const int h = blockIdx.x, b = blockIdx.y;
    const float alpha = __ldg(alpha_p);

    if (t < 128) { s_pr[t] = prior_at(prior, b, h, t); s_bin[t] = b_in[t]; }
    __syncthreads();

    {   // sB <- Win padded (1152 uint4)
        const uint4* src = (const uint4*)g_WinP;
        uint4* dst = (uint4*)sB;
#pragma unroll
        for (int i = 0; i < 5; i++) {
            int idx = t + i * 256;
            if (idx < 1152) dst[idx] = src[idx];
        }
    }
    {   // sA <- F_mod bf16 [c][w]
        const float* xrow = x + b * 1048576 + h * 128;
#pragma unroll
        for (int i = 0; i < 16; i++) {
            int idx = t + i * 256;           // 4096 = 64c x 64 wp
            int c = idx >> 6, wp = (idx & 63) * 2;
            float2 f = *(const float2*)&xrow[c * 16384 + wp];
            f.x += alpha * s_pr[wp];
            f.y += alpha * s_pr[wp + 1];
            *(__nv_bfloat162*)&sA[c * LDA1 + wp] = __float22bfloat162_rn(f);
        }
    }
    __syncthreads();

    // MMA: warp wid owns m-rows w0..w0+15, full N=128, K=64
    const int w0 = wid * 16;
    float acc[16][4];
#pragma unroll
    for (int nt = 0; nt < 16; nt++)
#pragma unroll
        for (int j = 0; j < 4; j++) acc[nt][j] = 0.f;

    const uint32_t sA_u = smem_u32(sA), sB_u = smem_u32(sB);
    const int m_row = (lid & 7) + ((lid >> 4) << 3);
    const int m_col = ((lid >> 3) & 1) << 3;
    const uint32_t a_base = sA_u + (uint32_t)((m_row * LDA1 + w0 + m_col) * 2);
    const uint32_t b_base = sB_u + (uint32_t)((m_row * LDB1 + m_col) * 2);

#pragma unroll
    for (int ks = 0; ks < 4; ks++) {
        uint32_t afr[4];
        ldsm_x4_trans(afr, a_base + (uint32_t)(ks * 16 * LDA1 * 2));
#pragma unroll
        for (int np = 0; np < 8; np++) {     // 2 n-tiles per x4 B-load
            uint32_t bfr[4];
            ldsm_x4(bfr, b_base + (uint32_t)((np * 16 * LDB1 + ks * 16) * 2));
            mma_bf16(acc[2 * np],     afr, bfr);
            mma_bf16(acc[2 * np + 1], afr, bfr + 2);
        }
    }
    __syncthreads();   // frags in regs; overlay sPb

    {   // acc (+bias) -> sPb[o][w] bf16
        const int g = lid >> 2, q2 = (lid & 3) * 2;
        const int w = w0 + g;
#pragma unroll
        for (int nt = 0; nt < 16; nt++) {
            int o = nt * 8 + q2;
            sPb[o * LDS1 + w]           = __float2bfloat16(acc[nt][0] + s_bin[o]);
            sPb[(o + 1) * LDS1 + w]     = __float2bfloat16(acc[nt][1] + s_bin[o + 1]);
            sPb[o * LDS1 + w + 8]       = __float2bfloat16(acc[nt][2] + s_bin[o]);
            sPb[(o + 1) * LDS1 + w + 8] = __float2bfloat16(acc[nt][3] + s_bin[o + 1]);
        }
    }
    __syncthreads();

    {   // coalesced x_proj write-out (2048 uint4)
        __nv_bfloat16* xp = g_xp + (b * 128 + h) * 16384;
#pragma unroll
        for (int i = 0; i < 8; i++) {
            int idx = t + i * 256;
            int o = idx >> 4, c8 = (idx & 15) * 8;
            *(uint4*)&xp[o * 128 + c8] = *(const uint4*)&sPb[o * LDS1 + c8];
        }
    }
}

// ---- K2: per-(b,o) plane: concurrent h-scan + v-scan, merge, store ----
// smem: sX @0, sH @32768, sV @65536, each [128][128] bf16. total 98304B -> 2 blocks/SM.
__global__ __launch_bounds__(256) void k2(const float* __restrict__ Bvec) {
    extern __shared__ __align__(16) char smch[];
    __nv_bfloat16* sX = (__nv_bfloat16*)smch;
    __nv_bfloat16* sH = (__nv_bfloat16*)(smch + 32768);
    __nv_bfloat16* sV = (__nv_bfloat16*)(smch + 65536);

    const int t = threadIdx.x;
    const int o = blockIdx.x, b = blockIdx.y;
    const float a = g_At[o], bv = __ldg(&Bvec[o]);
    const int gbase = b * 2097152 + o * 128;   // + h*16384 + w

    {   // load plane (2048 uint4)
        const __nv_bfloat16* src = g_xp + gbase;
#pragma unroll
        for (int i = 0; i < 8; i++) {
            int idx = t + i * 256;
            int h = idx >> 4, c8 = (idx & 15) * 8;
            *(uint4*)&sX[h * LDK2 + c8] = *(const uint4*)&src[h * 16384 + c8];
        }
    }
    __syncthreads();

    if (t < 128) {   // warps 0-3: h-scan row t -> sH
        const __nv_bfloat16* xr = &sX[t * LDK2];
        __nv_bfloat16* hr = &sH[t * LDK2];
        float st = 0.0f;
#pragma unroll 4
        for (int wb = 0; wb < 32; wb++) {
            uint2 u = *(const uint2*)&xr[wb * 4];
            float2 f0 = __bfloat1622float2(*(__nv_bfloat162*)&u.x);
            float2 f1 = __bfloat1622float2(*(__nv_bfloat162*)&u.y);
            st = fmaf(a, st, bv * f0.x); f0.x = st;
            st = fmaf(a, st, bv * f0.y); f0.y = st;
            st = fmaf(a, st, bv * f1.x); f1.x = st;
            st = fmaf(a, st, bv * f1.y); f1.y = st;
            __nv_bfloat162 p0 = __float22bfloat162_rn(f0);
            __nv_bfloat162 p1 = __float22bfloat162_rn(f1);
            *(uint2*)&hr[wb * 4] = make_uint2(*(uint32_t*)&p0, *(uint32_t*)&p1);
        }
    } else {         // warps 4-7: v-scan column w = t-128 -> sV
        const int w = t - 128;
        float st = 0.0f;
#pragma unroll 4
        for (int h = 0; h < 128; h++) {
            float xv = __bfloat162float(sX[h * LDK2 + w]);
            st = fmaf(a, st, bv * xv);
            sV[h * LDK2 + w] = __float2bfloat16(st);
        }
    }
    __syncthreads();

    {   // merge + store h_sum plane (2048 uint4)
        __nv_bfloat16* dst = g_hs + gbase;
#pragma unroll
        for (int i = 0; i < 8; i++) {
            int idx = t + i * 256;
            int h = idx >> 4, c8 = (idx & 15) * 8;
            uint4 uh = *(const uint4*)&sH[h * LDK2 + c8];
            uint4 uv = *(const uint4*)&sV[h * LDK2 + c8];
            uint4 r;
            *(__nv_bfloat162*)&r.x = __hadd2(*(__nv_bfloat162*)&uh.x, *(__nv_bfloat162*)&uv.x);
            *(__nv_bfloat162*)&r.y = __hadd2(*(__nv_bfloat162*)&uh.y, *(__nv_bfloat162*)&uv.y);
            *(__nv_bfloat162*)&r.z = __hadd2(*(__nv_bfloat162*)&uh.z, *(__nv_bfloat162*)&uv.z);
            *(__nv_bfloat162*)&r.w = __hadd2(*(__nv_bfloat162*)&uh.w, *(__nv_bfloat162*)&uv.w);
            *(uint4*)&dst[h * 16384 + c8] = r;
        }
    }
}

// ---- K3: per-(b,h): out = h_sum @ Wout^T (HMMA), fused fp32 epilogue ----
// x for the epilogue is prefetched into registers BEFORE the MMA phase so the
// DRAM latency overlaps staging+MMA instead of sitting on the critical path.
__global__ __launch_bounds__(256) void k3(
    const float* __restrict__ x, const float* __restrict__ prior,
    const float* __restrict__ b_out, const float* __restrict__ alpha_p,
    const float* __restrict__ gamma_p, float* __restrict__ out)
{
    extern __shared__ __align__(16) char smch[];
    __nv_bfloat16* sA = (__nv_bfloat16*)smch;
    __nv_bfloat16* sB = (__nv_bfloat16*)(smch + 34816);
    float* sR = (float*)smch;
    __shared__ float s_pr[128], s_bo[64];

    const int t = threadIdx.x;
    const int wid = t >> 5, lid = t & 31;
    const int h = blockIdx.x, b = blockIdx.y;
    const float alpha = __ldg(alpha_p), gamma = __ldg(gamma_p);

    if (t < 128) s_pr[t] = prior_at(prior, b, h, t);
    if (t < 64) s_bo[t] = b_out[t];

    // ---- prefetch epilogue x reads (8 x LDG.128, consumed after MMA) ----
    const int base_bh = b * 1048576 + h * 128;
    float4 xv[8];
#pragma unroll
    for (int i = 0; i < 8; i++) {
        int idx = t + i * 256;               // 2048 = 64c x 32 w4
        int c = idx >> 5, w4 = (idx & 31) * 4;
        xv[i] = *(const float4*)&x[base_bh + c * 16384 + w4];
    }

    {   // sB <- Wout padded (1088 uint4)
        const uint4* src = (const uint4*)g_WoutP;
        uint4* dst = (uint4*)sB;
#pragma unroll
        for (int i = 0; i < 5; i++) {
            int idx = t + i * 256;
            if (idx < 1088) dst[idx] = src[idx];
        }
    }
    {   // sA <- h_sum [o][w]
        const __nv_bfloat16* hs = g_hs + (b * 128 + h) * 16384;
#pragma unroll
        for (int i = 0; i < 8; i++) {
            int idx = t + i * 256;           // 2048 = 128o x 16 w8
            int o = idx >> 4, w8 = (idx & 15) * 8;
            *(uint4*)&sA[o * LDA3 + w8] = *(const uint4*)&hs[o * 128 + w8];
        }
    }
    __syncthreads();

    // MMA: M=128(w) x N=64(c) x K=128(o)
    const int w0 = wid * 16;
    float acc[8][4];
#pragma unroll
    for (int nt = 0; nt < 8; nt++)
#pragma unroll
        for (int j = 0; j < 4; j++) acc[nt][j] = 0.f;

    const uint32_t sA_u = smem_u32(sA), sB_u = smem_u32(sB);
    const int m_row = (lid & 7) + ((lid >> 4) << 3);
    const int m_col = ((lid >> 3) & 1) << 3;
    const uint32_t a_base = sA_u + (uint32_t)((m_row * LDA3 + w0 + m_col) * 2);
    const uint32_t b_base = sB_u + (uint32_t)((m_row * LDB3 + m_col) * 2);

#pragma unroll
    for (int ks = 0; ks < 8; ks++) {
        uint32_t afr[4];
        ldsm_x4_trans(afr, a_base + (uint32_t)(ks * 16 * LDA3 * 2));
#pragma unroll
        for (int np = 0; np < 4; np++) {     // 2 n-tiles per x4 B-load
            uint32_t bfr[4];
            ldsm_x4(bfr, b_base + (uint32_t)((np * 16 * LDB3 + ks * 16) * 2));
            mma_bf16(acc[2 * np],     afr, bfr);
            mma_bf16(acc[2 * np + 1], afr, bfr + 2);
        }
    }
    __syncthreads();   // overlay sR

    {   // acc -> sR[c][w]
        const int g = lid >> 2, q2 = (lid & 3) * 2;
        const int w = w0 + g;
#pragma unroll
        for (int nt = 0; nt < 8; nt++) {
            int c = nt * 8 + q2;
            sR[c * LDP + w]           = acc[nt][0];
            sR[(c + 1) * LDP + w]     = acc[nt][1];
            sR[c * LDP + w + 8]       = acc[nt][2];
            sR[(c + 1) * LDP + w + 8] = acc[nt][3];
        }
    }
    __syncthreads();

    {   // fused epilogue, float4: out = x + alpha*pr + gamma*(res + b_out)
#pragma unroll
        for (int i = 0; i < 8; i++) {
            int idx = t + i * 256;           // 2048 = 64c x 32 w4
            int c = idx >> 5, w4 = (idx & 31) * 4;
            int gb = base_bh + c * 16384 + w4;
            float4 rv = *(const float4*)&sR[c * LDP + w4];
            float4 pv = *(const float4*)&s_pr[w4];
            float bo = s_bo[c];
            float4 r;
            r.x = fmaf(alpha, pv.x, xv[i].x) + gamma * (rv.x + bo);
            r.y = fmaf(alpha, pv.y, xv[i].y) + gamma * (rv.y + bo);
            r.z = fmaf(alpha, pv.z, xv[i].z) + gamma * (rv.z + bo);
            r.w = fmaf(alpha, pv.w, xv[i].w) + gamma * (rv.w + bo);
            *(float4*)&out[gb] = r;
        }
    }
}

extern "C" void kernel_launch(void* const* d_in, const int* in_sizes, int n_in,
                              void* d_out, int out_size) {
    const float* x      = (const float*)d_in[0];
    const float* prior  = (const float*)d_in[1];
    const float* W_in   = (const float*)d_in[2];
    const float* b_in   = (const float*)d_in[3];
    const float* A      = (const float*)d_in[4];
    const float* B      = (const float*)d_in[5];
    const float* alpha  = (const float*)d_in[6];
    const float* gamma  = (const float*)d_in[7];
    const float* W_out  = (const float*)d_in[8];
    const float* b_out  = (const float*)d_in[9];
    float* out = (float*)d_out;

    const int smem_k1 = 35840;
    const int smem_k2 = 98304;
    const int smem_k3 = 34816 + 17408;   // 52224

    cudaFuncSetAttribute(k1, cudaFuncAttributeMaxDynamicSharedMemorySize, smem_k1);
    cudaFuncSetAttribute(k2, cudaFuncAttributeMaxDynamicSharedMemorySize, smem_k2);
    cudaFuncSetAttribute(k3, cudaFuncAttributeMaxDynamicSharedMemorySize, smem_k3);

    k_setup<<<32, 256>>>(W_in, W_out, A);
    dim3 grid(HDIM, BSZ);
    k1<<<grid, 256, smem_k1>>>(x, prior, b_in, alpha);
    k2<<<grid, 256, smem_k2>>>(B);
    k3<<<grid, 256, smem_k3>>>(x, prior, b_out, alpha, gamma, out);
}

// round 11
// speedup vs baseline: 1.3839x; 1.3839x over previous
#include <cuda_runtime.h>
#include <cuda_bf16.h>
#include <cstdint>

#define BSZ 8
#define CDIM 64
#define HDIM 128
#define WDIM 128
#define HID 128

// smem strides (bf16 elems)
#define LDA1 136   // K1 A: [c][w], 64 rows (ldmatrix pad)
#define LDB1 72    // K1 B: [o][c], 128 rows
#define LDS1 136   // K1 staging [o][w] bf16
#define LDA3 136   // K3 A: [o][w], 128 rows
#define LDB3 136   // K3 B: [c][o], 64 rows
#define LDP  132   // K3 fp32 staging [c][w]
#define LDK2 136   // K2 planes [h][w] bf16 — 272B row stride staggers banks (4-way max)

// ---- scratch (device globals; allocation-free) ----
__device__ __nv_bfloat16 g_xp[BSZ*HDIM*HID*WDIM];  // x_proj [b][h][o][w] bf16
__device__ __nv_bfloat16 g_hs[BSZ*HDIM*HID*WDIM];  // h_sum  [b][h][o][w] bf16

__device__ __forceinline__ uint32_t smem_u32(const void* p) {
    return (uint32_t)__cvta_generic_to_shared(p);
}

// ---- ldmatrix / mma.sync wrappers (sm_80-portable) ----
__device__ __forceinline__ void ldsm_x4_trans(uint32_t* r, uint32_t a) {
    asm volatile("ldmatrix.sync.aligned.m8n8.x4.trans.shared.b16 {%0,%1,%2,%3}, [%4];"
        : "=r"(r[0]), "=r"(r[1]), "=r"(r[2]), "=r"(r[3]) : "r"(a));
}
__device__ __forceinline__ void ldsm_x4(uint32_t* r, uint32_t a) {
    asm volatile("ldmatrix.sync.aligned.m8n8.x4.shared.b16 {%0,%1,%2,%3}, [%4];"
        : "=r"(r[0]), "=r"(r[1]), "=r"(r[2]), "=r"(r[3]) : "r"(a));
}
__device__ __forceinline__ void mma_bf16(float* d, const uint32_t* a, const uint32_t* b) {
    asm volatile("mma.sync.aligned.m16n8k16.row.col.f32.bf16.bf16.f32 "
        "{%0,%1,%2,%3}, {%4,%5,%6,%7}, {%8,%9}, {%0,%1,%2,%3};"
        : "+f"(d[0]), "+f"(d[1]), "+f"(d[2]), "+f"(d[3])
        : "r"(a[0]), "r"(a[1]), "r"(a[2]), "r"(a[3]), "r"(b[0]), "r"(b[1]));
}

// ---- bilinear prior 32->128, align_corners, clip ----
__device__ __forceinline__ float prior_at(const float* __restrict__ prior,
                                          int b, int h, int w) {
    const float s = 31.0f / 127.0f;
    float ys = h * s, xs = w * s;
    int y0 = (int)ys, x0 = (int)xs;
    int y1 = min(y0 + 1, 31), x1 = min(x0 + 1, 31);
    float wy = ys - (float)y0, wx = xs - (float)x0;
    const float* p = prior + b * 1024;
    float p00 = p[y0*32+x0], p01 = p[y0*32+x1];
    float p10 = p[y1*32+x0], p11 = p[y1*32+x1];
    float top = p00 + (p01 - p00) * wx;
    float bot = p10 + (p10 - p10) * 0.0f + (p11 - p10) * wx;
    float v = top + (bot - top) * wy;
    return fminf(1.0f, fmaxf(-1.0f, v));
}

// ---- K1: per-(b,h): x_proj = F_mod @ Win^T + b_in (HMMA) ----
// smem: sA [64c][136w] bf16 17408B @0 ; sB [128o][72c] bf16 18432B @17408
//       sPb [128o][136w] bf16 34816B overlays sA after MMA. total 35840B.
__global__ __launch_bounds__(256) void k1(
    const float* __restrict__ x, const float* __restrict__ prior,
    const float* __restrict__ Win, const float* __restrict__ b_in,
    const float* __restrict__ alpha_p)
{
    extern __shared__ __align__(16) char smch[];
    __nv_bfloat16* sA = (__nv_bfloat16*)smch;
    __nv_bfloat16* sB = (__nv_bfloat16*)(smch + 17408);
    __nv_bfloat16* sPb = (__nv_bfloat16*)smch;
    __shared__ float s_pr[128], s_bin[128];

    const int t = threadIdx.x;
    const int wid = t >> 5, lid = t & 31;
    const int h = blockIdx.x, b = blockIdx.y;
    const float alpha = __ldg(alpha_p);

    // ---- prefetch x (16 x LDG.64); consumed after the smem staging below ----
    const float* xrow = x + b * 1048576 + h * 128;
    float2 xv[16];
#pragma unroll
    for (int i = 0; i < 16; i++) {
        int idx = t + i * 256;               // 4096 = 64c x 64 wp
        int c = idx >> 6, wp = (idx & 63) * 2;
        xv[i] = *(const float2*)&xrow[c * 16384 + wp];
    }

    if (t < 128) { s_pr[t] = prior_at(prior, b, h, t); s_bin[t] = b_in[t]; }

    {   // sB <- Win fp32 -> bf16 padded (8192 elems, 16 float2/thread)
#pragma unroll
        for (int i = 0; i < 16; i++) {
            int idx = t + i * 256;           // 8192 = 128o x 32 c-pairs
            int o = idx >> 5, c2 = (idx & 31) * 2;
            float2 wv = *(const float2*)&Win[o * 64 + c2];
            *(__nv_bfloat162*)&sB[o * LDB1 + c2] = __float22bfloat162_rn(wv);
        }
    }
    __syncthreads();

    {   // sA <- F_mod bf16 [c][w] from prefetched xv
#pragma unroll
        for (int i = 0; i < 16; i++) {
            int idx = t + i * 256;
            int c = idx >> 6, wp = (idx & 63) * 2;
            float2 f = xv[i];
            f.x += alpha * s_pr[wp];
            f.y += alpha * s_pr[wp + 1];
            *(__nv_bfloat162*)&sA[c * LDA1 + wp] = __float22bfloat162_rn(f);
        }
    }
    __syncthreads();

    // MMA: warp wid owns m-rows w0..w0+15, full N=128, K=64
    const int w0 = wid * 16;
    float acc[16][4];
#pragma unroll
    for (int nt = 0; nt < 16; nt++)
#pragma unroll
        for (int j = 0; j < 4; j++) acc[nt][j] = 0.f;

    const uint32_t sA_u = smem_u32(sA), sB_u = smem_u32(sB);
    const int m_row = (lid & 7) + ((lid >> 4) << 3);
    const int m_col = ((lid >> 3) & 1) << 3;
    const uint32_t a_base = sA_u + (uint32_t)((m_row * LDA1 + w0 + m_col) * 2);
    const uint32_t b_base = sB_u + (uint32_t)((m_row * LDB1 + m_col) * 2);

#pragma unroll
    for (int ks = 0; ks < 4; ks++) {
        uint32_t afr[4];
        ldsm_x4_trans(afr, a_base + (uint32_t)(ks * 16 * LDA1 * 2));
#pragma unroll
        for (int np = 0; np < 8; np++) {     // 2 n-tiles per x4 B-load
            uint32_t bfr[4];
            ldsm_x4(bfr, b_base + (uint32_t)((np * 16 * LDB1 + ks * 16) * 2));
            mma_bf16(acc[2 * np],     afr, bfr);
            mma_bf16(acc[2 * np + 1], afr, bfr + 2);
        }
    }
    __syncthreads();   // frags in regs; overlay sPb

    {   // acc (+bias) -> sPb[o][w] bf16
        const int g = lid >> 2, q2 = (lid & 3) * 2;
        const int w = w0 + g;
#pragma unroll
        for (int nt = 0; nt < 16; nt++) {
            int o = nt * 8 + q2;
            sPb[o * LDS1 + w]           = __float2bfloat16(acc[nt][0] + s_bin[o]);
            sPb[(o + 1) * LDS1 + w]     = __float2bfloat16(acc[nt][1] + s_bin[o + 1]);
            sPb[o * LDS1 + w + 8]       = __float2bfloat16(acc[nt][2] + s_bin[o]);
            sPb[(o + 1) * LDS1 + w + 8] = __float2bfloat16(acc[nt][3] + s_bin[o + 1]);
        }
    }
    __syncthreads();

    {   // coalesced x_proj write-out (2048 uint4)
        __nv_bfloat16* xp = g_xp + (b * 128 + h) * 16384;
#pragma unroll
        for (int i = 0; i < 8; i++) {
            int idx = t + i * 256;
            int o = idx >> 4, c8 = (idx & 15) * 8;
            *(uint4*)&xp[o * 128 + c8] = *(const uint4*)&sPb[o * LDS1 + c8];
        }
    }
}

// ---- K2: per-(b,o) plane: concurrent h-scan + v-scan, merge, store ----
// smem: sX @0, sH @34816, sV @69632, each [128][136] bf16. total 104448B (2 blocks/SM).
__global__ __launch_bounds__(256) void k2(const float* __restrict__ A,
                                          const float* __restrict__ Bvec) {
    extern __shared__ __align__(16) char smch[];
    __nv_bfloat16* sX = (__nv_bfloat16*)smch;
    __nv_bfloat16* sH = (__nv_bfloat16*)(smch + 34816);
    __nv_bfloat16* sV = (__nv_bfloat16*)(smch + 69632);

    const int t = threadIdx.x;
    const int o = blockIdx.x, b = blockIdx.y;
    const float a = tanhf(__ldg(&A[o]));
    const float bv = __ldg(&Bvec[o]);
    const int gbase = b * 2097152 + o * 128;   // + h*16384 + w

    {   // load plane (2048 uint4)
        const __nv_bfloat16* src = g_xp + gbase;
#pragma unroll
        for (int i = 0; i < 8; i++) {
            int idx = t + i * 256;
            int h = idx >> 4, c8 = (idx & 15) * 8;
            *(uint4*)&sX[h * LDK2 + c8] = *(const uint4*)&src[h * 16384 + c8];
        }
    }
    __syncthreads();

    if (t < 128) {   // warps 0-3: h-scan row t -> sH
        const __nv_bfloat16* xr = &sX[t * LDK2];
        __nv_bfloat16* hr = &sH[t * LDK2];
        float st = 0.0f;
#pragma unroll 4
        for (int wb = 0; wb < 32; wb++) {
            uint2 u = *(const uint2*)&xr[wb * 4];
            float2 f0 = __bfloat1622float2(*(__nv_bfloat162*)&u.x);
            float2 f1 = __bfloat1622float2(*(__nv_bfloat162*)&u.y);
            st = fmaf(a, st, bv * f0.x); f0.x = st;
            st = fmaf(a, st, bv * f0.y); f0.y = st;
            st = fmaf(a, st, bv * f1.x); f1.x = st;
            st = fmaf(a, st, bv * f1.y); f1.y = st;
            __nv_bfloat162 p0 = __float22bfloat162_rn(f0);
            __nv_bfloat162 p1 = __float22bfloat162_rn(f1);
            *(uint2*)&hr[wb * 4] = make_uint2(*(uint32_t*)&p0, *(uint32_t*)&p1);
        }
    } else {         // warps 4-7: v-scan column w = t-128 -> sV
        const int w = t - 128;
        float st = 0.0f;
#pragma unroll 4
        for (int h = 0; h < 128; h++) {
            float xvv = __bfloat162float(sX[h * LDK2 + w]);
            st = fmaf(a, st, bv * xvv);
            sV[h * LDK2 + w] = __float2bfloat16(st);
        }
    }
    __syncthreads();

    {   // merge + store h_sum plane (2048 uint4)
        __nv_bfloat16* dst = g_hs + gbase;
#pragma unroll
        for (int i = 0; i < 8; i++) {
            int idx = t + i * 256;
            int h = idx >> 4, c8 = (idx & 15) * 8;
            uint4 uh = *(const uint4*)&sH[h * LDK2 + c8];
            uint4 uv = *(const uint4*)&sV[h * LDK2 + c8];
            uint4 r;
            *(__nv_bfloat162*)&r.x = __hadd2(*(__nv_bfloat162*)&uh.x, *(__nv_bfloat162*)&uv.x);
            *(__nv_bfloat162*)&r.y = __hadd2(*(__nv_bfloat162*)&uh.y, *(__nv_bfloat162*)&uv.y);
            *(__nv_bfloat162*)&r.z = __hadd2(*(__nv_bfloat162*)&uh.z, *(__nv_bfloat162*)&uv.z);
            *(__nv_bfloat162*)&r.w = __hadd2(*(__nv_bfloat162*)&uh.w, *(__nv_bfloat162*)&uv.w);
            *(uint4*)&dst[h * 16384 + c8] = r;
        }
    }
}

// ---- K3: per-(b,h): out = h_sum @ Wout^T (HMMA), fused fp32 epilogue ----
__global__ __launch_bounds__(256) void k3(
    const float* __restrict__ x, const float* __restrict__ prior,
    const float* __restrict__ Wout, const float* __restrict__ b_out,
    const float* __restrict__ alpha_p, const float* __restrict__ gamma_p,
    float* __restrict__ out)
{
    extern __shared__ __align__(16) char smch[];
    __nv_bfloat16* sA = (__nv_bfloat16*)smch;
    __nv_bfloat16* sB = (__nv_bfloat16*)(smch + 34816);
    float* sR = (float*)smch;
    __shared__ float s_pr[128], s_bo[64];

    const int t = threadIdx.x;
    const int wid = t >> 5, lid = t & 31;
    const int h = blockIdx.x, b = blockIdx.y;
    const float alpha = __ldg(alpha_p), gamma = __ldg(gamma_p);

    if (t < 128) s_pr[t] = prior_at(prior, b, h, t);
    if (t < 64) s_bo[t] = b_out[t];

    // ---- prefetch epilogue x reads (8 x LDG.128, consumed after MMA) ----
    const int base_bh = b * 1048576 + h * 128;
    float4 xv[8];
#pragma unroll
    for (int i = 0; i < 8; i++) {
        int idx = t + i * 256;               // 2048 = 64c x 32 w4
        int c = idx >> 5, w4 = (idx & 31) * 4;
        xv[i] = *(const float4*)&x[base_bh + c * 16384 + w4];
    }

    {   // sB <- Wout fp32 -> bf16 padded (8192 elems)
#pragma unroll
        for (int i = 0; i < 16; i++) {
            int idx = t + i * 256;           // 8192 = 64c x 64 o-pairs
            int c = idx >> 6, o2 = (idx & 63) * 2;
            float2 wv = *(const float2*)&Wout[c * 128 + o2];
            *(__nv_bfloat162*)&sB[c * LDB3 + o2] = __float22bfloat162_rn(wv);
        }
    }
    {   // sA <- h_sum [o][w]
        const __nv_bfloat16* hs = g_hs + (b * 128 + h) * 16384;
#pragma unroll
        for (int i = 0; i < 8; i++) {
            int idx = t + i * 256;           // 2048 = 128o x 16 w8
            int o = idx >> 4, w8 = (idx & 15) * 8;
            *(uint4*)&sA[o * LDA3 + w8] = *(const uint4*)&hs[o * 128 + w8];
        }
    }
    __syncthreads();

    // MMA: M=128(w) x N=64(c) x K=128(o)
    const int w0 = wid * 16;
    float acc[8][4];
#pragma unroll
    for (int nt = 0; nt < 8; nt++)
#pragma unroll
        for (int j = 0; j < 4; j++) acc[nt][j] = 0.f;

    const uint32_t sA_u = smem_u32(sA), sB_u = smem_u32(sB);
    const int m_row = (lid & 7) + ((lid >> 4) << 3);
    const int m_col = ((lid >> 3) & 1) << 3;
    const uint32_t a_base = sA_u + (uint32_t)((m_row * LDA3 + w0 + m_col) * 2);
    const uint32_t b_base = sB_u + (uint32_t)((m_row * LDB3 + m_col) * 2);

#pragma unroll
    for (int ks = 0; ks < 8; ks++) {
        uint32_t afr[4];
        ldsm_x4_trans(afr, a_base + (uint32_t)(ks * 16 * LDA3 * 2));
#pragma unroll
        for (int np = 0; np < 4; np++) {     // 2 n-tiles per x4 B-load
            uint32_t bfr[4];
            ldsm_x4(bfr, b_base + (uint32_t)((np * 16 * LDB3 + ks * 16) * 2));
            mma_bf16(acc[2 * np],     afr, bfr);
            mma_bf16(acc[2 * np + 1], afr, bfr + 2);
        }
    }
    __syncthreads();   // overlay sR

    {   // acc -> sR[c][w]
        const int g = lid >> 2, q2 = (lid & 3) * 2;
        const int w = w0 + g;
#pragma unroll
        for (int nt = 0; nt < 8; nt++) {
            int c = nt * 8 + q2;
            sR[c * LDP + w]           = acc[nt][0];
            sR[(c + 1) * LDP + w]     = acc[nt][1];
            sR[c * LDP + w + 8]       = acc[nt][2];
            sR[(c + 1) * LDP + w + 8] = acc[nt][3];
        }
    }
    __syncthreads();

    {   // fused epilogue, float4: out = x + alpha*pr + gamma*(res + b_out)
#pragma unroll
        for (int i = 0; i < 8; i++) {
            int idx = t + i * 256;           // 2048 = 64c x 32 w4
            int c = idx >> 5, w4 = (idx & 31) * 4;
            int gb = base_bh + c * 16384 + w4;
            float4 rv = *(const float4*)&sR[c * LDP + w4];
            float4 pv = *(const float4*)&s_pr[w4];
            float bo = s_bo[c];
            float4 r;
            r.x = fmaf(alpha, pv.x, xv[i].x) + gamma * (rv.x + bo);
            r.y = fmaf(alpha, pv.y, xv[i].y) + gamma * (rv.y + bo);
            r.z = fmaf(alpha, pv.z, xv[i].z) + gamma * (rv.z + bo);
            r.w = fmaf(alpha, pv.w, xv[i].w) + gamma * (rv.w + bo);
            *(float4*)&out[gb] = r;
        }
    }
}

extern "C" void kernel_launch(void* const* d_in, const int* in_sizes, int n_in,
                              void* d_out, int out_size) {
    const float* x      = (const float*)d_in[0];
    const float* prior  = (const float*)d_in[1];
    const float* W_in   = (const float*)d_in[2];
    const float* b_in   = (const float*)d_in[3];
    const float* A      = (const float*)d_in[4];
    const float* B      = (const float*)d_in[5];
    const float* alpha  = (const float*)d_in[6];
    const float* gamma  = (const float*)d_in[7];
    const float* W_out  = (const float*)d_in[8];
    const float* b_out  = (const float*)d_in[9];
    float* out = (float*)d_out;

    const int smem_k1 = 35840;
    const int smem_k2 = 104448;
    const int smem_k3 = 34816 + 17408;   // 52224

    cudaFuncSetAttribute(k1, cudaFuncAttributeMaxDynamicSharedMemorySize, smem_k1);
    cudaFuncSetAttribute(k2, cudaFuncAttributeMaxDynamicSharedMemorySize, smem_k2);
    cudaFuncSetAttribute(k3, cudaFuncAttributeMaxDynamicSharedMemorySize, smem_k3);

    dim3 grid(HDIM, BSZ);
    k1<<<grid, 256, smem_k1>>>(x, prior, W_in, b_in, alpha);
    k2<<<grid, 256, smem_k2>>>(A, B);
    k3<<<grid, 256, smem_k3>>>(x, prior, W_out, b_out, alpha, gamma, out);
}

// round 12
// speedup vs baseline: 1.5005x; 1.0843x over previous
#include <cuda_runtime.h>
#include <cuda_bf16.h>
#include <cstdint>

#define BSZ 8
#define CDIM 64
#define HDIM 128
#define WDIM 128
#define HID 128

// smem strides (bf16 elems)
#define LDA1 136   // K1 A: [c][w], 64 rows (ldmatrix pad)
#define LDB1 72    // K1 B: [o][c], 128 rows
#define LDS1 136   // K1 staging [o][w] bf16
#define LDA3 136   // K3 A: [o][w], 128 rows
#define LDB3 136   // K3 B: [c][o], 64 rows
#define LDP  132   // K3 fp32 staging [c][w]
#define LDK2 136   // K2 planes [h][w] bf16 — 272B row stride staggers banks

// ---- scratch (device globals; allocation-free) ----
__device__ __nv_bfloat16 g_xp[BSZ*HDIM*HID*WDIM];  // x_proj [b][h][o][w] bf16
__device__ __nv_bfloat16 g_hs[BSZ*HDIM*HID*WDIM];  // h_sum  [b][h][o][w] bf16

__device__ __forceinline__ uint32_t smem_u32(const void* p) {
    return (uint32_t)__cvta_generic_to_shared(p);
}

// ---- cp.async (sm_80-portable LDGSTS) ----
#define CP_ASYNC16(dst, src) \
    asm volatile("cp.async.cg.shared.global [%0], [%1], 16;" \
                 :: "r"(dst), "l"(src) : "memory")
#define CP_COMMIT() asm volatile("cp.async.commit_group;" ::: "memory")
#define CP_WAIT0()  asm volatile("cp.async.wait_group 0;" ::: "memory")

// ---- ldmatrix / mma.sync wrappers (sm_80-portable) ----
__device__ __forceinline__ void ldsm_x4_trans(uint32_t* r, uint32_t a) {
    asm volatile("ldmatrix.sync.aligned.m8n8.x4.trans.shared.b16 {%0,%1,%2,%3}, [%4];"
        : "=r"(r[0]), "=r"(r[1]), "=r"(r[2]), "=r"(r[3]) : "r"(a));
}
__device__ __forceinline__ void ldsm_x4(uint32_t* r, uint32_t a) {
    asm volatile("ldmatrix.sync.aligned.m8n8.x4.shared.b16 {%0,%1,%2,%3}, [%4];"
        : "=r"(r[0]), "=r"(r[1]), "=r"(r[2]), "=r"(r[3]) : "r"(a));
}
__device__ __forceinline__ void mma_bf16(float* d, const uint32_t* a, const uint32_t* b) {
    asm volatile("mma.sync.aligned.m16n8k16.row.col.f32.bf16.bf16.f32 "
        "{%0,%1,%2,%3}, {%4,%5,%6,%7}, {%8,%9}, {%0,%1,%2,%3};"
        : "+f"(d[0]), "+f"(d[1]), "+f"(d[2]), "+f"(d[3])
        : "r"(a[0]), "r"(a[1]), "r"(a[2]), "r"(a[3]), "r"(b[0]), "r"(b[1]));
}

// ---- bilinear prior 32->128, align_corners, clip ----
__device__ __forceinline__ float prior_at(const float* __restrict__ prior,
                                          int b, int h, int w) {
    const float s = 31.0f / 127.0f;
    float ys = h * s, xs = w * s;
    int y0 = (int)ys, x0 = (int)xs;
    int y1 = min(y0 + 1, 31), x1 = min(x0 + 1, 31);
    float wy = ys - (float)y0, wx = xs - (float)x0;
    const float* p = prior + b * 1024;
    float p00 = p[y0*32+x0], p01 = p[y0*32+x1];
    float p10 = p[y1*32+x0], p11 = p[y1*32+x1];
    float top = p00 + (p01 - p00) * wx;
    float bot = p10 + (p11 - p10) * wx;
    float v = top + (bot - top) * wy;
    return fminf(1.0f, fmaxf(-1.0f, v));
}

// ---- K1: per-(b,h): x_proj = F_mod @ Win^T + b_in (HMMA) ----
// smem: sXf fp32 [64c][128w] 32768B @0 (cp.async target)
//       sA  bf16 [64c][136w] 17408B @32768
//       sB  bf16 [128o][72c] 18432B @50176          total 68608B (3 blocks/SM)
//       sPb bf16 [128o][136w] 34816B overlays sXf after MMA.
__global__ __launch_bounds__(256) void k1(
    const float* __restrict__ x, const float* __restrict__ prior,
    const float* __restrict__ Win, const float* __restrict__ b_in,
    const float* __restrict__ alpha_p)
{
    extern __shared__ __align__(16) char smch[];
    float* sXf = (float*)smch;
    __nv_bfloat16* sA = (__nv_bfloat16*)(smch + 32768);
    __nv_bfloat16* sB = (__nv_bfloat16*)(smch + 50176);
    __nv_bfloat16* sPb = (__nv_bfloat16*)smch;
    __shared__ float s_pr[128], s_bin[128];

    const int t = threadIdx.x;
    const int wid = t >> 5, lid = t & 31;
    const int h = blockIdx.x, b = blockIdx.y;
    const float alpha = __ldg(alpha_p);

    // ---- async-stage x row (32KB) into sXf; latency hidden behind staging ----
    {
        const float* xrow = x + b * 1048576 + h * 128;
        const uint32_t sXf_u = smem_u32(sXf);
#pragma unroll
        for (int i = 0; i < 8; i++) {
            int idx = t + i * 256;           // 2048 chunks = 64c x 32
            int c = idx >> 5, ch = (idx & 31) * 4;
            CP_ASYNC16(sXf_u + (uint32_t)(idx * 16), &xrow[c * 16384 + ch]);
        }
        CP_COMMIT();
    }

    if (t < 128) { s_pr[t] = prior_at(prior, b, h, t); s_bin[t] = b_in[t]; }

    {   // sB <- Win fp32 -> bf16 padded (8192 elems)
#pragma unroll
        for (int i = 0; i < 16; i++) {
            int idx = t + i * 256;           // 8192 = 128o x 32 c-pairs
            int o = idx >> 5, c2 = (idx & 31) * 2;
            float2 wv = *(const float2*)&Win[o * 64 + c2];
            *(__nv_bfloat162*)&sB[o * LDB1 + c2] = __float22bfloat162_rn(wv);
        }
    }
    CP_WAIT0();
    __syncthreads();

    {   // sA <- F_mod bf16 [c][w] from sXf
#pragma unroll
        for (int i = 0; i < 16; i++) {
            int idx = t + i * 256;           // 4096 = 64c x 64 wp
            int c = idx >> 6, wp = (idx & 63) * 2;
            float2 f = *(const float2*)&sXf[c * 128 + wp];
            f.x += alpha * s_pr[wp];
            f.y += alpha * s_pr[wp + 1];
            *(__nv_bfloat162*)&sA[c * LDA1 + wp] = __float22bfloat162_rn(f);
        }
    }
    __syncthreads();

    // MMA: warp wid owns m-rows w0..w0+15, full N=128, K=64
    const int w0 = wid * 16;
    float acc[16][4];
#pragma unroll
    for (int nt = 0; nt < 16; nt++)
#pragma unroll
        for (int j = 0; j < 4; j++) acc[nt][j] = 0.f;

    const uint32_t sA_u = smem_u32(sA), sB_u = smem_u32(sB);
    const int m_row = (lid & 7) + ((lid >> 4) << 3);
    const int m_col = ((lid >> 3) & 1) << 3;
    const uint32_t a_base = sA_u + (uint32_t)((m_row * LDA1 + w0 + m_col) * 2);
    const uint32_t b_base = sB_u + (uint32_t)((m_row * LDB1 + m_col) * 2);

#pragma unroll
    for (int ks = 0; ks < 4; ks++) {
        uint32_t afr[4];
        ldsm_x4_trans(afr, a_base + (uint32_t)(ks * 16 * LDA1 * 2));
#pragma unroll
        for (int np = 0; np < 8; np++) {
            uint32_t bfr[4];
            ldsm_x4(bfr, b_base + (uint32_t)((np * 16 * LDB1 + ks * 16) * 2));
            mma_bf16(acc[2 * np],     afr, bfr);
            mma_bf16(acc[2 * np + 1], afr, bfr + 2);
        }
    }
    __syncthreads();   // frags in regs; overlay sPb

    {   // acc (+bias) -> sPb[o][w] bf16
        const int g = lid >> 2, q2 = (lid & 3) * 2;
        const int w = w0 + g;
#pragma unroll
        for (int nt = 0; nt < 16; nt++) {
            int o = nt * 8 + q2;
            sPb[o * LDS1 + w]           = __float2bfloat16(acc[nt][0] + s_bin[o]);
            sPb[(o + 1) * LDS1 + w]     = __float2bfloat16(acc[nt][1] + s_bin[o + 1]);
            sPb[o * LDS1 + w + 8]       = __float2bfloat16(acc[nt][2] + s_bin[o]);
            sPb[(o + 1) * LDS1 + w + 8] = __float2bfloat16(acc[nt][3] + s_bin[o + 1]);
        }
    }
    __syncthreads();

    {   // coalesced x_proj write-out (2048 uint4)
        __nv_bfloat16* xp = g_xp + (b * 128 + h) * 16384;
#pragma unroll
        for (int i = 0; i < 8; i++) {
            int idx = t + i * 256;
            int o = idx >> 4, c8 = (idx & 15) * 8;
            *(uint4*)&xp[o * 128 + c8] = *(const uint4*)&sPb[o * LDS1 + c8];
        }
    }
}

// ---- K2: per-(b,o) plane: concurrent h-scan + v-scan, merge, store ----
// smem: sX @0, sH @34816, sV @69632, each [128][136] bf16. total 104448B.
__global__ __launch_bounds__(256) void k2(const float* __restrict__ A,
                                          const float* __restrict__ Bvec) {
    extern __shared__ __align__(16) char smch[];
    __nv_bfloat16* sX = (__nv_bfloat16*)smch;
    __nv_bfloat16* sH = (__nv_bfloat16*)(smch + 34816);
    __nv_bfloat16* sV = (__nv_bfloat16*)(smch + 69632);

    const int t = threadIdx.x;
    const int o = blockIdx.x, b = blockIdx.y;
    const float a = tanhf(__ldg(&A[o]));
    const float bv = __ldg(&Bvec[o]);
    const int gbase = b * 2097152 + o * 128;   // + h*16384 + w

    {   // async load plane (2048 x 16B)
        const __nv_bfloat16* src = g_xp + gbase;
        const uint32_t sX_u = smem_u32(sX);
#pragma unroll
        for (int i = 0; i < 8; i++) {
            int idx = t + i * 256;
            int h = idx >> 4, c8 = (idx & 15) * 8;
            CP_ASYNC16(sX_u + (uint32_t)((h * LDK2 + c8) * 2), &src[h * 16384 + c8]);
        }
        CP_COMMIT(); CP_WAIT0();
    }
    __syncthreads();

    if (t < 128) {   // warps 0-3: h-scan row t -> sH
        const __nv_bfloat16* xr = &sX[t * LDK2];
        __nv_bfloat16* hr = &sH[t * LDK2];
        float st = 0.0f;
#pragma unroll 4
        for (int wb = 0; wb < 32; wb++) {
            uint2 u = *(const uint2*)&xr[wb * 4];
            float2 f0 = __bfloat1622float2(*(__nv_bfloat162*)&u.x);
            float2 f1 = __bfloat1622float2(*(__nv_bfloat162*)&u.y);
            st = fmaf(a, st, bv * f0.x); f0.x = st;
            st = fmaf(a, st, bv * f0.y); f0.y = st;
            st = fmaf(a, st, bv * f1.x); f1.x = st;
            st = fmaf(a, st, bv * f1.y); f1.y = st;
            __nv_bfloat162 p0 = __float22bfloat162_rn(f0);
            __nv_bfloat162 p1 = __float22bfloat162_rn(f1);
            *(uint2*)&hr[wb * 4] = make_uint2(*(uint32_t*)&p0, *(uint32_t*)&p1);
        }
    } else {         // warps 4-7: v-scan column w = t-128 -> sV
        const int w = t - 128;
        float st = 0.0f;
#pragma unroll 4
        for (int h = 0; h < 128; h++) {
            float xvv = __bfloat162float(sX[h * LDK2 + w]);
            st = fmaf(a, st, bv * xvv);
            sV[h * LDK2 + w] = __float2bfloat16(st);
        }
    }
    __syncthreads();

    {   // merge + store h_sum plane (2048 uint4)
        __nv_bfloat16* dst = g_hs + gbase;
#pragma unroll
        for (int i = 0; i < 8; i++) {
            int idx = t + i * 256;
            int h = idx >> 4, c8 = (idx & 15) * 8;
            uint4 uh = *(const uint4*)&sH[h * LDK2 + c8];
            uint4 uv = *(const uint4*)&sV[h * LDK2 + c8];
            uint4 r;
            *(__nv_bfloat162*)&r.x = __hadd2(*(__nv_bfloat162*)&uh.x, *(__nv_bfloat162*)&uv.x);
            *(__nv_bfloat162*)&r.y = __hadd2(*(__nv_bfloat162*)&uh.y, *(__nv_bfloat162*)&uv.y);
            *(__nv_bfloat162*)&r.z = __hadd2(*(__nv_bfloat162*)&uh.z, *(__nv_bfloat162*)&uv.z);
            *(__nv_bfloat162*)&r.w = __hadd2(*(__nv_bfloat162*)&uh.w, *(__nv_bfloat162*)&uv.w);
            *(uint4*)&dst[h * 16384 + c8] = r;
        }
    }
}

// ---- K3: per-(b,h): out = h_sum @ Wout^T (HMMA), fused fp32 epilogue ----
__global__ __launch_bounds__(256) void k3(
    const float* __restrict__ x, const float* __restrict__ prior,
    const float* __restrict__ Wout, const float* __restrict__ b_out,
    const float* __restrict__ alpha_p, const float* __restrict__ gamma_p,
    float* __restrict__ out)
{
    extern __shared__ __align__(16) char smch[];
    __nv_bfloat16* sA = (__nv_bfloat16*)smch;
    __nv_bfloat16* sB = (__nv_bfloat16*)(smch + 34816);
    float* sR = (float*)smch;
    __shared__ float s_pr[128], s_bo[64];

    const int t = threadIdx.x;
    const int wid = t >> 5, lid = t & 31;
    const int h = blockIdx.x, b = blockIdx.y;
    const float alpha = __ldg(alpha_p), gamma = __ldg(gamma_p);

    {   // async-stage sA <- h_sum [o][w] (2048 x 16B)
        const __nv_bfloat16* hs = g_hs + (b * 128 + h) * 16384;
        const uint32_t sA_u0 = smem_u32(sA);
#pragma unroll
        for (int i = 0; i < 8; i++) {
            int idx = t + i * 256;
            int o = idx >> 4, w8 = (idx & 15) * 8;
            CP_ASYNC16(sA_u0 + (uint32_t)((o * LDA3 + w8) * 2), &hs[o * 128 + w8]);
        }
        CP_COMMIT();
    }

    if (t < 128) s_pr[t] = prior_at(prior, b, h, t);
    if (t < 64) s_bo[t] = b_out[t];

    // ---- prefetch epilogue x reads (8 x LDG.128, consumed after MMA) ----
    const int base_bh = b * 1048576 + h * 128;
    float4 xv[8];
#pragma unroll
    for (int i = 0; i < 8; i++) {
        int idx = t + i * 256;               // 2048 = 64c x 32 w4
        int c = idx >> 5, w4 = (idx & 31) * 4;
        xv[i] = *(const float4*)&x[base_bh + c * 16384 + w4];
    }

    {   // sB <- Wout fp32 -> bf16 padded (8192 elems)
#pragma unroll
        for (int i = 0; i < 16; i++) {
            int idx = t + i * 256;           // 8192 = 64c x 64 o-pairs
            int c = idx >> 6, o2 = (idx & 63) * 2;
            float2 wv = *(const float2*)&Wout[c * 128 + o2];
            *(__nv_bfloat162*)&sB[c * LDB3 + o2] = __float22bfloat162_rn(wv);
        }
    }
    CP_WAIT0();
    __syncthreads();

    // MMA: M=128(w) x N=64(c) x K=128(o)
    const int w0 = wid * 16;
    float acc[8][4];
#pragma unroll
    for (int nt = 0; nt < 8; nt++)
#pragma unroll
        for (int j = 0; j < 4; j++) acc[nt][j] = 0.f;

    const uint32_t sA_u = smem_u32(sA), sB_u = smem_u32(sB);
    const int m_row = (lid & 7) + ((lid >> 4) << 3);
    const int m_col = ((lid >> 3) & 1) << 3;
    const uint32_t a_base = sA_u + (uint32_t)((m_row * LDA3 + w0 + m_col) * 2);
    const uint32_t b_base = sB_u + (uint32_t)((m_row * LDB3 + m_col) * 2);

#pragma unroll
    for (int ks = 0; ks < 8; ks++) {
        uint32_t afr[4];
        ldsm_x4_trans(afr, a_base + (uint32_t)(ks * 16 * LDA3 * 2));
#pragma unroll
        for (int np = 0; np < 4; np++) {
            uint32_t bfr[4];
            ldsm_x4(bfr, b_base + (uint32_t)((np * 16 * LDB3 + ks * 16) * 2));
            mma_bf16(acc[2 * np],     afr, bfr);
            mma_bf16(acc[2 * np + 1], afr, bfr + 2);
        }
    }
    __syncthreads();   // overlay sR

    {   // acc -> sR[c][w]
        const int g = lid >> 2, q2 = (lid & 3) * 2;
        const int w = w0 + g;
#pragma unroll
        for (int nt = 0; nt < 8; nt++) {
            int c = nt * 8 + q2;
            sR[c * LDP + w]           = acc[nt][0];
            sR[(c + 1) * LDP + w]     = acc[nt][1];
            sR[c * LDP + w + 8]       = acc[nt][2];
            sR[(c + 1) * LDP + w + 8] = acc[nt][3];
        }
    }
    __syncthreads();

    {   // fused epilogue, float4: out = x + alpha*pr + gamma*(res + b_out)
#pragma unroll
        for (int i = 0; i < 8; i++) {
            int idx = t + i * 256;           // 2048 = 64c x 32 w4
            int c = idx >> 5, w4 = (idx & 31) * 4;
            int gb = base_bh + c * 16384 + w4;
            float4 rv = *(const float4*)&sR[c * LDP + w4];
            float4 pv = *(const float4*)&s_pr[w4];
            float bo = s_bo[c];
            float4 r;
            r.x = fmaf(alpha, pv.x, xv[i].x) + gamma * (rv.x + bo);
            r.y = fmaf(alpha, pv.y, xv[i].y) + gamma * (rv.y + bo);
            r.z = fmaf(alpha, pv.z, xv[i].z) + gamma * (rv.z + bo);
            r.w = fmaf(alpha, pv.w, xv[i].w) + gamma * (rv.w + bo);
            *(float4*)&out[gb] = r;
        }
    }
}

extern "C" void kernel_launch(void* const* d_in, const int* in_sizes, int n_in,
                              void* d_out, int out_size) {
    const float* x      = (const float*)d_in[0];
    const float* prior  = (const float*)d_in[1];
    const float* W_in   = (const float*)d_in[2];
    const float* b_in   = (const float*)d_in[3];
    const float* A      = (const float*)d_in[4];
    const float* B      = (const float*)d_in[5];
    const float* alpha  = (const float*)d_in[6];
    const float* gamma  = (const float*)d_in[7];
    const float* W_out  = (const float*)d_in[8];
    const float* b_out  = (const float*)d_in[9];
    float* out = (float*)d_out;

    const int smem_k1 = 68608;
    const int smem_k2 = 104448;
    const int smem_k3 = 34816 + 17408;   // 52224

    cudaFuncSetAttribute(k1, cudaFuncAttributeMaxDynamicSharedMemorySize, smem_k1);
    cudaFuncSetAttribute(k2, cudaFuncAttributeMaxDynamicSharedMemorySize, smem_k2);
    cudaFuncSetAttribute(k3, cudaFuncAttributeMaxDynamicSharedMemorySize, smem_k3);

    dim3 grid(HDIM, BSZ);
    k1<<<grid, 256, smem_k1>>>(x, prior, W_in, b_in, alpha);
    k2<<<grid, 256, smem_k2>>>(A, B);
    k3<<<grid, 256, smem_k3>>>(x, prior, W_out, b_out, alpha, gamma, out);
}

// round 13
// speedup vs baseline: 1.5206x; 1.0134x over previous
#include <cuda_runtime.h>
#include <cuda_bf16.h>
#include <cstdint>

#define BSZ 8
#define CDIM 64
#define HDIM 128
#define WDIM 128
#define HID 128

// smem strides (bf16 elems)
#define LDA1 136   // K1 A: [c][w], 64 rows (ldmatrix pad)
#define LDB1 72    // K1 B: [o][c], 128 rows
#define LDS1 136   // K1 staging [o][w] bf16
#define LDA3 136   // K3 A: [o][w], 128 rows
#define LDB3 136   // K3 B: [c][o], 64 rows
#define LDP  132   // K3 fp32 staging [c][w]
#define LDK2 136   // K2 planes [h][w] bf16 — 272B row stride staggers banks

// ---- scratch (device globals; allocation-free) ----
__device__ __nv_bfloat16 g_xp[BSZ*HDIM*HID*WDIM];  // x_proj [b][h][o][w] bf16
__device__ __nv_bfloat16 g_hs[BSZ*HDIM*HID*WDIM];  // h_sum  [b][h][o][w] bf16

__device__ __forceinline__ uint32_t smem_u32(const void* p) {
    return (uint32_t)__cvta_generic_to_shared(p);
}

// ---- cp.async (sm_80-portable LDGSTS) ----
#define CP_ASYNC16(dst, src) \
    asm volatile("cp.async.cg.shared.global [%0], [%1], 16;" \
                 :: "r"(dst), "l"(src) : "memory")
#define CP_COMMIT() asm volatile("cp.async.commit_group;" ::: "memory")
#define CP_WAIT0()  asm volatile("cp.async.wait_group 0;" ::: "memory")

// ---- ldmatrix / mma.sync wrappers (sm_80-portable) ----
__device__ __forceinline__ void ldsm_x4_trans(uint32_t* r, uint32_t a) {
    asm volatile("ldmatrix.sync.aligned.m8n8.x4.trans.shared.b16 {%0,%1,%2,%3}, [%4];"
        : "=r"(r[0]), "=r"(r[1]), "=r"(r[2]), "=r"(r[3]) : "r"(a));
}
__device__ __forceinline__ void ldsm_x4(uint32_t* r, uint32_t a) {
    asm volatile("ldmatrix.sync.aligned.m8n8.x4.shared.b16 {%0,%1,%2,%3}, [%4];"
        : "=r"(r[0]), "=r"(r[1]), "=r"(r[2]), "=r"(r[3]) : "r"(a));
}
__device__ __forceinline__ void mma_bf16(float* d, const uint32_t* a, const uint32_t* b) {
    asm volatile("mma.sync.aligned.m16n8k16.row.col.f32.bf16.bf16.f32 "
        "{%0,%1,%2,%3}, {%4,%5,%6,%7}, {%8,%9}, {%0,%1,%2,%3};"
        : "+f"(d[0]), "+f"(d[1]), "+f"(d[2]), "+f"(d[3])
        : "r"(a[0]), "r"(a[1]), "r"(a[2]), "r"(a[3]), "r"(b[0]), "r"(b[1]));
}

// ---- bilinear prior 32->128, align_corners, clip ----
__device__ __forceinline__ float prior_at(const float* __restrict__ prior,
                                          int b, int h, int w) {
    const float s = 31.0f / 127.0f;
    float ys = h * s, xs = w * s;
    int y0 = (int)ys, x0 = (int)xs;
    int y1 = min(y0 + 1, 31), x1 = min(x0 + 1, 31);
    float wy = ys - (float)y0, wx = xs - (float)x0;
    const float* p = prior + b * 1024;
    float p00 = p[y0*32+x0], p01 = p[y0*32+x1];
    float p10 = p[y1*32+x0], p11 = p[y1*32+x1];
    float top = p00 + (p01 - p00) * wx;
    float bot = p10 + (p11 - p10) * wx;
    float v = top + (bot - top) * wy;
    return fminf(1.0f, fmaxf(-1.0f, v));
}

// ---- K1: per-(b,h): x_proj = F_mod @ Win^T + b_in (HMMA), 512 threads ----
// 16 warps: warp = (m-tile wid&7, n-half wid>>3). acc[8][4] -> ~60 regs.
// smem: sXf fp32 32768B @0 ; sA bf16 17408B @32768 ; sB bf16 18432B @50176
//       sPb bf16 34816B overlays sXf after MMA. total 68608B.
__global__ __launch_bounds__(512) void k1(
    const float* __restrict__ x, const float* __restrict__ prior,
    const float* __restrict__ Win, const float* __restrict__ b_in,
    const float* __restrict__ alpha_p)
{
    extern __shared__ __align__(16) char smch[];
    float* sXf = (float*)smch;
    __nv_bfloat16* sA = (__nv_bfloat16*)(smch + 32768);
    __nv_bfloat16* sB = (__nv_bfloat16*)(smch + 50176);
    __nv_bfloat16* sPb = (__nv_bfloat16*)smch;
    __shared__ float s_pr[128], s_bin[128];

    const int t = threadIdx.x;
    const int wid = t >> 5, lid = t & 31;
    const int h = blockIdx.x, b = blockIdx.y;
    const float alpha = __ldg(alpha_p);

    {   // async-stage x row (32KB), 4 x 16B per thread
        const float* xrow = x + b * 1048576 + h * 128;
        const uint32_t sXf_u = smem_u32(sXf);
#pragma unroll
        for (int i = 0; i < 4; i++) {
            int idx = t + i * 512;           // 2048 chunks = 64c x 32
            int c = idx >> 5, ch = (idx & 31) * 4;
            CP_ASYNC16(sXf_u + (uint32_t)(idx * 16), &xrow[c * 16384 + ch]);
        }
        CP_COMMIT();
    }

    if (t < 128) { s_pr[t] = prior_at(prior, b, h, t); s_bin[t] = b_in[t]; }

    {   // sB <- Win fp32 -> bf16 padded (8192 elems, 8 float2/thread)
#pragma unroll
        for (int i = 0; i < 8; i++) {
            int idx = t + i * 512;           // 4096 = 128o x 32 c-pairs
            int o = idx >> 5, c2 = (idx & 31) * 2;
            float2 wv = *(const float2*)&Win[o * 64 + c2];
            *(__nv_bfloat162*)&sB[o * LDB1 + c2] = __float22bfloat162_rn(wv);
        }
    }
    CP_WAIT0();
    __syncthreads();

    {   // sA <- F_mod bf16 [c][w] from sXf
#pragma unroll
        for (int i = 0; i < 8; i++) {
            int idx = t + i * 512;           // 4096 = 64c x 64 wp
            int c = idx >> 6, wp = (idx & 63) * 2;
            float2 f = *(const float2*)&sXf[c * 128 + wp];
            f.x += alpha * s_pr[wp];
            f.y += alpha * s_pr[wp + 1];
            *(__nv_bfloat162*)&sA[c * LDA1 + wp] = __float22bfloat162_rn(f);
        }
    }
    __syncthreads();

    // MMA: warp = m-rows w0..w0+15 x n-cols [nh*64, nh*64+64), K=64
    const int w0 = (wid & 7) * 16;
    const int nh = wid >> 3;
    float acc[8][4];
#pragma unroll
    for (int nt = 0; nt < 8; nt++)
#pragma unroll
        for (int j = 0; j < 4; j++) acc[nt][j] = 0.f;

    const uint32_t sA_u = smem_u32(sA), sB_u = smem_u32(sB);
    const int m_row = (lid & 7) + ((lid >> 4) << 3);
    const int m_col = ((lid >> 3) & 1) << 3;
    const uint32_t a_base = sA_u + (uint32_t)((m_row * LDA1 + w0 + m_col) * 2);
    const uint32_t b_base = sB_u + (uint32_t)(((nh * 64 + m_row) * LDB1 + m_col) * 2);

#pragma unroll
    for (int ks = 0; ks < 4; ks++) {
        uint32_t afr[4];
        ldsm_x4_trans(afr, a_base + (uint32_t)(ks * 16 * LDA1 * 2));
#pragma unroll
        for (int np = 0; np < 4; np++) {
            uint32_t bfr[4];
            ldsm_x4(bfr, b_base + (uint32_t)((np * 16 * LDB1 + ks * 16) * 2));
            mma_bf16(acc[2 * np],     afr, bfr);
            mma_bf16(acc[2 * np + 1], afr, bfr + 2);
        }
    }
    __syncthreads();   // frags in regs; overlay sPb

    {   // acc (+bias) -> sPb[o][w] bf16
        const int g = lid >> 2, q2 = (lid & 3) * 2;
        const int w = w0 + g;
#pragma unroll
        for (int nt = 0; nt < 8; nt++) {
            int o = nh * 64 + nt * 8 + q2;
            sPb[o * LDS1 + w]           = __float2bfloat16(acc[nt][0] + s_bin[o]);
            sPb[(o + 1) * LDS1 + w]     = __float2bfloat16(acc[nt][1] + s_bin[o + 1]);
            sPb[o * LDS1 + w + 8]       = __float2bfloat16(acc[nt][2] + s_bin[o]);
            sPb[(o + 1) * LDS1 + w + 8] = __float2bfloat16(acc[nt][3] + s_bin[o + 1]);
        }
    }
    __syncthreads();

    {   // coalesced x_proj write-out (2048 uint4, 4/thread)
        __nv_bfloat16* xp = g_xp + (b * 128 + h) * 16384;
#pragma unroll
        for (int i = 0; i < 4; i++) {
            int idx = t + i * 512;
            int o = idx >> 4, c8 = (idx & 15) * 8;
            *(uint4*)&xp[o * 128 + c8] = *(const uint4*)&sPb[o * LDS1 + c8];
        }
    }
}

// ---- K2: per-(b,o) plane: concurrent h-scan + v-scan, merge, store ----
// smem: sX @0, sH @34816, sV @69632, each [128][136] bf16. total 104448B.
__global__ __launch_bounds__(256) void k2(const float* __restrict__ A,
                                          const float* __restrict__ Bvec) {
    extern __shared__ __align__(16) char smch[];
    __nv_bfloat16* sX = (__nv_bfloat16*)smch;
    __nv_bfloat16* sH = (__nv_bfloat16*)(smch + 34816);
    __nv_bfloat16* sV = (__nv_bfloat16*)(smch + 69632);

    const int t = threadIdx.x;
    const int o = blockIdx.x, b = blockIdx.y;
    const float a = tanhf(__ldg(&A[o]));
    const float bv = __ldg(&Bvec[o]);
    const int gbase = b * 2097152 + o * 128;   // + h*16384 + w

    {   // async load plane (2048 x 16B)
        const __nv_bfloat16* src = g_xp + gbase;
        const uint32_t sX_u = smem_u32(sX);
#pragma unroll
        for (int i = 0; i < 8; i++) {
            int idx = t + i * 256;
            int h = idx >> 4, c8 = (idx & 15) * 8;
            CP_ASYNC16(sX_u + (uint32_t)((h * LDK2 + c8) * 2), &src[h * 16384 + c8]);
        }
        CP_COMMIT(); CP_WAIT0();
    }
    __syncthreads();

    if (t < 128) {   // warps 0-3: h-scan row t -> sH
        const __nv_bfloat16* xr = &sX[t * LDK2];
        __nv_bfloat16* hr = &sH[t * LDK2];
        float st = 0.0f;
#pragma unroll 4
        for (int wb = 0; wb < 32; wb++) {
            uint2 u = *(const uint2*)&xr[wb * 4];
            float2 f0 = __bfloat1622float2(*(__nv_bfloat162*)&u.x);
            float2 f1 = __bfloat1622float2(*(__nv_bfloat162*)&u.y);
            st = fmaf(a, st, bv * f0.x); f0.x = st;
            st = fmaf(a, st, bv * f0.y); f0.y = st;
            st = fmaf(a, st, bv * f1.x); f1.x = st;
            st = fmaf(a, st, bv * f1.y); f1.y = st;
            __nv_bfloat162 p0 = __float22bfloat162_rn(f0);
            __nv_bfloat162 p1 = __float22bfloat162_rn(f1);
            *(uint2*)&hr[wb * 4] = make_uint2(*(uint32_t*)&p0, *(uint32_t*)&p1);
        }
    } else {         // warps 4-7: v-scan column w = t-128 -> sV
        const int w = t - 128;
        float st = 0.0f;
#pragma unroll 4
        for (int h = 0; h < 128; h++) {
            float xvv = __bfloat162float(sX[h * LDK2 + w]);
            st = fmaf(a, st, bv * xvv);
            sV[h * LDK2 + w] = __float2bfloat16(st);
        }
    }
    __syncthreads();

    {   // merge + store h_sum plane (2048 uint4)
        __nv_bfloat16* dst = g_hs + gbase;
#pragma unroll
        for (int i = 0; i < 8; i++) {
            int idx = t + i * 256;
            int h = idx >> 4, c8 = (idx & 15) * 8;
            uint4 uh = *(const uint4*)&sH[h * LDK2 + c8];
            uint4 uv = *(const uint4*)&sV[h * LDK2 + c8];
            uint4 r;
            *(__nv_bfloat162*)&r.x = __hadd2(*(__nv_bfloat162*)&uh.x, *(__nv_bfloat162*)&uv.x);
            *(__nv_bfloat162*)&r.y = __hadd2(*(__nv_bfloat162*)&uh.y, *(__nv_bfloat162*)&uv.y);
            *(__nv_bfloat162*)&r.z = __hadd2(*(__nv_bfloat162*)&uh.z, *(__nv_bfloat162*)&uv.z);
            *(__nv_bfloat162*)&r.w = __hadd2(*(__nv_bfloat162*)&uh.w, *(__nv_bfloat162*)&uv.w);
            *(uint4*)&dst[h * 16384 + c8] = r;
        }
    }
}

// ---- K3: per-(b,h): out = h_sum @ Wout^T (HMMA), fused fp32 epilogue ----
__global__ __launch_bounds__(256) void k3(
    const float* __restrict__ x, const float* __restrict__ prior,
    const float* __restrict__ Wout, const float* __restrict__ b_out,
    const float* __restrict__ alpha_p, const float* __restrict__ gamma_p,
    float* __restrict__ out)
{
    extern __shared__ __align__(16) char smch[];
    __nv_bfloat16* sA = (__nv_bfloat16*)smch;
    __nv_bfloat16* sB = (__nv_bfloat16*)(smch + 34816);
    float* sR = (float*)smch;
    __shared__ float s_pr[128], s_bo[64];

    const int t = threadIdx.x;
    const int wid = t >> 5, lid = t & 31;
    const int h = blockIdx.x, b = blockIdx.y;
    const float alpha = __ldg(alpha_p), gamma = __ldg(gamma_p);

    {   // async-stage sA <- h_sum [o][w] (2048 x 16B)
        const __nv_bfloat16* hs = g_hs + (b * 128 + h) * 16384;
        const uint32_t sA_u0 = smem_u32(sA);
#pragma unroll
        for (int i = 0; i < 8; i++) {
            int idx = t + i * 256;
            int o = idx >> 4, w8 = (idx & 15) * 8;
            CP_ASYNC16(sA_u0 + (uint32_t)((o * LDA3 + w8) * 2), &hs[o * 128 + w8]);
        }
        CP_COMMIT();
    }

    if (t < 128) s_pr[t] = prior_at(prior, b, h, t);
    if (t < 64) s_bo[t] = b_out[t];

    // ---- prefetch epilogue x reads (8 x LDG.128, consumed after MMA) ----
    const int base_bh = b * 1048576 + h * 128;
    float4 xv[8];
#pragma unroll
    for (int i = 0; i < 8; i++) {
        int idx = t + i * 256;               // 2048 = 64c x 32 w4
        int c = idx >> 5, w4 = (idx & 31) * 4;
        xv[i] = *(const float4*)&x[base_bh + c * 16384 + w4];
    }

    {   // sB <- Wout fp32 -> bf16 padded (8192 elems)
#pragma unroll
        for (int i = 0; i < 16; i++) {
            int idx = t + i * 256;           // 8192 = 64c x 64 o-pairs
            int c = idx >> 6, o2 = (idx & 63) * 2;
            float2 wv = *(const float2*)&Wout[c * 128 + o2];
            *(__nv_bfloat162*)&sB[c * LDB3 + o2] = __float22bfloat162_rn(wv);
        }
    }
    CP_WAIT0();
    __syncthreads();

    // MMA: M=128(w) x N=64(c) x K=128(o)
    const int w0 = wid * 16;
    float acc[8][4];
#pragma unroll
    for (int nt = 0; nt < 8; nt++)
#pragma unroll
        for (int j = 0; j < 4; j++) acc[nt][j] = 0.f;

    const uint32_t sA_u = smem_u32(sA), sB_u = smem_u32(sB);
    const int m_row = (lid & 7) + ((lid >> 4) << 3);
    const int m_col = ((lid >> 3) & 1) << 3;
    const uint32_t a_base = sA_u + (uint32_t)((m_row * LDA3 + w0 + m_col) * 2);
    const uint32_t b_base = sB_u + (uint32_t)((m_row * LDB3 + m_col) * 2);

#pragma unroll
    for (int ks = 0; ks < 8; ks++) {
        uint32_t afr[4];
        ldsm_x4_trans(afr, a_base + (uint32_t)(ks * 16 * LDA3 * 2));
#pragma unroll
        for (int np = 0; np < 4; np++) {
            uint32_t bfr[4];
            ldsm_x4(bfr, b_base + (uint32_t)((np * 16 * LDB3 + ks * 16) * 2));
            mma_bf16(acc[2 * np],     afr, bfr);
            mma_bf16(acc[2 * np + 1], afr, bfr + 2);
        }
    }
    __syncthreads();   // overlay sR

    {   // acc -> sR[c][w]
        const int g = lid >> 2, q2 = (lid & 3) * 2;
        const int w = w0 + g;
#pragma unroll
        for (int nt = 0; nt < 8; nt++) {
            int c = nt * 8 + q2;
            sR[c * LDP + w]           = acc[nt][0];
            sR[(c + 1) * LDP + w]     = acc[nt][1];
            sR[c * LDP + w + 8]       = acc[nt][2];
            sR[(c + 1) * LDP + w + 8] = acc[nt][3];
        }
    }
    __syncthreads();

    {   // fused epilogue, float4: out = x + alpha*pr + gamma*(res + b_out)
#pragma unroll
        for (int i = 0; i < 8; i++) {
            int idx = t + i * 256;           // 2048 = 64c x 32 w4
            int c = idx >> 5, w4 = (idx & 31) * 4;
            int gb = base_bh + c * 16384 + w4;
            float4 rv = *(const float4*)&sR[c * LDP + w4];
            float4 pv = *(const float4*)&s_pr[w4];
            float bo = s_bo[c];
            float4 r;
            r.x = fmaf(alpha, pv.x, xv[i].x) + gamma * (rv.x + bo);
            r.y = fmaf(alpha, pv.y, xv[i].y) + gamma * (rv.y + bo);
            r.z = fmaf(alpha, pv.z, xv[i].z) + gamma * (rv.z + bo);
            r.w = fmaf(alpha, pv.w, xv[i].w) + gamma * (rv.w + bo);
            *(float4*)&out[gb] = r;
        }
    }
}

extern "C" void kernel_launch(void* const* d_in, const int* in_sizes, int n_in,
                              void* d_out, int out_size) {
    const float* x      = (const float*)d_in[0];
    const float* prior  = (const float*)d_in[1];
    const float* W_in   = (const float*)d_in[2];
    const float* b_in   = (const float*)d_in[3];
    const float* A      = (const float*)d_in[4];
    const float* B      = (const float*)d_in[5];
    const float* alpha  = (const float*)d_in[6];
    const float* gamma  = (const float*)d_in[7];
    const float* W_out  = (const float*)d_in[8];
    const float* b_out  = (const float*)d_in[9];
    float* out = (float*)d_out;

    const int smem_k1 = 68608;
    const int smem_k2 = 104448;
    const int smem_k3 = 34816 + 17408;   // 52224

    cudaFuncSetAttribute(k1, cudaFuncAttributeMaxDynamicSharedMemorySize, smem_k1);
    cudaFuncSetAttribute(k2, cudaFuncAttributeMaxDynamicSharedMemorySize, smem_k2);
    cudaFuncSetAttribute(k3, cudaFuncAttributeMaxDynamicSharedMemorySize, smem_k3);

    dim3 grid(HDIM, BSZ);
    k1<<<grid, 512, smem_k1>>>(x, prior, W_in, b_in, alpha);
    k2<<<grid, 256, smem_k2>>>(A, B);
    k3<<<grid, 256, smem_k3>>>(x, prior, W_out, b_out, alpha, gamma, out);
}

// round 14
// speedup vs baseline: 1.5253x; 1.0031x over previous
#include <cuda_runtime.h>
#include <cuda_bf16.h>
#include <cstdint>

#define BSZ 8
#define CDIM 64
#define HDIM 128
#define WDIM 128
#define HID 128

// smem strides (bf16 elems)
#define LDA1 136   // K1 F_mod: [c][w], 64 rows (B operand, trans)
#define LDB1 72    // K1 Win:   [o][c], 128 rows (A operand)
#define LDS1 136   // K1 staging [o][w] bf16
#define LDA3 136   // K3 h_sum: [o][w], 128 rows (B operand, trans)
#define LDB3 136   // K3 Wout:  [c][o], 64 rows (A operand)
#define LDP  132   // K3 fp32 staging [c][w]
#define LDK2 136   // K2 planes [h][w] bf16

// ---- scratch (device globals; allocation-free) ----
__device__ __nv_bfloat16 g_xp[BSZ*HDIM*HID*WDIM];  // x_proj [b][h][o][w] bf16
__device__ __nv_bfloat16 g_hs[BSZ*HDIM*HID*WDIM];  // h_sum  [b][h][o][w] bf16

__device__ __forceinline__ uint32_t smem_u32(const void* p) {
    return (uint32_t)__cvta_generic_to_shared(p);
}

// ---- cp.async ----
#define CP_ASYNC16(dst, src) \
    asm volatile("cp.async.cg.shared.global [%0], [%1], 16;" \
                 :: "r"(dst), "l"(src) : "memory")
#define CP_COMMIT() asm volatile("cp.async.commit_group;" ::: "memory")
#define CP_WAIT0()  asm volatile("cp.async.wait_group 0;" ::: "memory")

// ---- ldmatrix / mma.sync wrappers ----
__device__ __forceinline__ void ldsm_x4_trans(uint32_t* r, uint32_t a) {
    asm volatile("ldmatrix.sync.aligned.m8n8.x4.trans.shared.b16 {%0,%1,%2,%3}, [%4];"
        : "=r"(r[0]), "=r"(r[1]), "=r"(r[2]), "=r"(r[3]) : "r"(a));
}
__device__ __forceinline__ void ldsm_x4(uint32_t* r, uint32_t a) {
    asm volatile("ldmatrix.sync.aligned.m8n8.x4.shared.b16 {%0,%1,%2,%3}, [%4];"
        : "=r"(r[0]), "=r"(r[1]), "=r"(r[2]), "=r"(r[3]) : "r"(a));
}
__device__ __forceinline__ void mma_bf16(float* d, const uint32_t* a, const uint32_t* b) {
    asm volatile("mma.sync.aligned.m16n8k16.row.col.f32.bf16.bf16.f32 "
        "{%0,%1,%2,%3}, {%4,%5,%6,%7}, {%8,%9}, {%0,%1,%2,%3};"
        : "+f"(d[0]), "+f"(d[1]), "+f"(d[2]), "+f"(d[3])
        : "r"(a[0]), "r"(a[1]), "r"(a[2]), "r"(a[3]), "r"(b[0]), "r"(b[1]));
}

// ---- bilinear prior 32->128, align_corners, clip ----
__device__ __forceinline__ float prior_at(const float* __restrict__ prior,
                                          int b, int h, int w) {
    const float s = 31.0f / 127.0f;
    float ys = h * s, xs = w * s;
    int y0 = (int)ys, x0 = (int)xs;
    int y1 = min(y0 + 1, 31), x1 = min(x0 + 1, 31);
    float wy = ys - (float)y0, wx = xs - (float)x0;
    const float* p = prior + b * 1024;
    float p00 = p[y0*32+x0], p01 = p[y0*32+x1];
    float p10 = p[y1*32+x0], p11 = p[y1*32+x1];
    float top = p00 + (p01 - p00) * wx;
    float bot = p10 + (p11 - p10) * wx;
    float v = top + (bot - top) * wy;
    return fminf(1.0f, fmaxf(-1.0f, v));
}

// ---- K1: per-(b,h): x_proj = F_mod @ Win^T + b_in (HMMA), 512 threads ----
// MMA orientation m=o, n=w: D fragments land w-contiguous -> STS.32 epilogue.
// smem: sXf fp32 32768B @0 ; sF bf16 [c][w] 17408B @32768 ; sW bf16 [o][c] 18432B @50176
//       sPb bf16 [o][w] 34816B overlays sXf after MMA. total 68608B.
__global__ __launch_bounds__(512) void k1(
    const float* __restrict__ x, const float* __restrict__ prior,
    const float* __restrict__ Win, const float* __restrict__ b_in,
    const float* __restrict__ alpha_p)
{
    extern __shared__ __align__(16) char smch[];
    float* sXf = (float*)smch;
    __nv_bfloat16* sF = (__nv_bfloat16*)(smch + 32768);
    __nv_bfloat16* sW = (__nv_bfloat16*)(smch + 50176);
    __nv_bfloat16* sPb = (__nv_bfloat16*)smch;
    __shared__ float s_pr[128], s_bin[128];

    const int t = threadIdx.x;
    const int wid = t >> 5, lid = t & 31;
    const int h = blockIdx.x, b = blockIdx.y;
    const float alpha = __ldg(alpha_p);

    {   // async-stage x row (32KB), 4 x 16B per thread
        const float* xrow = x + b * 1048576 + h * 128;
        const uint32_t sXf_u = smem_u32(sXf);
#pragma unroll
        for (int i = 0; i < 4; i++) {
            int idx = t + i * 512;           // 2048 chunks = 64c x 32
            int c = idx >> 5, ch = (idx & 31) * 4;
            CP_ASYNC16(sXf_u + (uint32_t)(idx * 16), &xrow[c * 16384 + ch]);
        }
        CP_COMMIT();
    }

    if (t < 128) { s_pr[t] = prior_at(prior, b, h, t); s_bin[t] = b_in[t]; }

    {   // sW <- Win fp32 -> bf16 (LDG.128 + STS.64, 4/thread)
#pragma unroll
        for (int i = 0; i < 4; i++) {
            int idx = t + i * 512;           // 2048 = 128o x 16 c4-groups
            int o = idx >> 4, c4 = (idx & 15) * 4;
            float4 wv = *(const float4*)&Win[o * 64 + c4];
            __nv_bfloat162 p0 = __float22bfloat162_rn(make_float2(wv.x, wv.y));
            __nv_bfloat162 p1 = __float22bfloat162_rn(make_float2(wv.z, wv.w));
            *(uint2*)&sW[o * LDB1 + c4] = make_uint2(*(uint32_t*)&p0, *(uint32_t*)&p1);
        }
    }
    CP_WAIT0();
    __syncthreads();

    {   // sF <- F_mod bf16 [c][w] from sXf (LDS.128 + STS.64, 4/thread)
#pragma unroll
        for (int i = 0; i < 4; i++) {
            int idx = t + i * 512;           // 2048 = 64c x 32 w4-groups
            int c = idx >> 5, w4 = (idx & 31) * 4;
            float4 f = *(const float4*)&sXf[c * 128 + w4];
            float4 pv = *(const float4*)&s_pr[w4];
            f.x += alpha * pv.x; f.y += alpha * pv.y;
            f.z += alpha * pv.z; f.w += alpha * pv.w;
            __nv_bfloat162 p0 = __float22bfloat162_rn(make_float2(f.x, f.y));
            __nv_bfloat162 p1 = __float22bfloat162_rn(make_float2(f.z, f.w));
            *(uint2*)&sF[c * LDA1 + w4] = make_uint2(*(uint32_t*)&p0, *(uint32_t*)&p1);
        }
    }
    __syncthreads();

    // MMA: m=o (16 warps = 8 m-tiles x 2 w-halves), n=w, K=64
    const int o0 = (wid & 7) * 16;
    const int nh = wid >> 3;
    float acc[8][4];
#pragma unroll
    for (int nt = 0; nt < 8; nt++)
#pragma unroll
        for (int j = 0; j < 4; j++) acc[nt][j] = 0.f;

    const uint32_t sF_u = smem_u32(sF), sW_u = smem_u32(sW);
    // A (Win [m=o][k=c], non-trans): lanes 0-15 rows m0-15 @k0, 16-31 @k8
    const uint32_t a_base = sW_u +
        (uint32_t)(((o0 + (lid & 15)) * LDB1 + ((lid >> 4) << 3)) * 2);
    // B (F [k=c][n=w], trans): lanes 0-7 k0-7@n0, 8-15 k8-15@n0, 16-31 @n8
    const int b_row = (lid & 7) + (((lid >> 3) & 1) << 3);
    const int b_col = nh * 64 + ((lid >> 4) << 3);
    const uint32_t b_base = sF_u + (uint32_t)((b_row * LDA1 + b_col) * 2);

#pragma unroll
    for (int ks = 0; ks < 4; ks++) {
        uint32_t afr[4];
        ldsm_x4(afr, a_base + (uint32_t)(ks * 16 * 2));
#pragma unroll
        for (int nt16 = 0; nt16 < 4; nt16++) {
            uint32_t bfr[4];
            ldsm_x4_trans(bfr, b_base + (uint32_t)((ks * 16 * LDA1 + nt16 * 16) * 2));
            mma_bf16(acc[2 * nt16],     afr, bfr);
            mma_bf16(acc[2 * nt16 + 1], afr, bfr + 2);
        }
    }
    __syncthreads();   // frags in regs; overlay sPb

    {   // acc (+bias) -> sPb[o][w], w-contiguous bf162 (16 STS.32/thread)
        const int g = lid >> 2, q2 = (lid & 3) * 2;
        const int oA = o0 + g, oB = o0 + g + 8;
        const float bA = s_bin[oA], bB = s_bin[oB];
#pragma unroll
        for (int nt = 0; nt < 8; nt++) {
            int w = nh * 64 + nt * 8 + q2;
            __nv_bfloat162 pA = __float22bfloat162_rn(
                make_float2(acc[nt][0] + bA, acc[nt][1] + bA));
            __nv_bfloat162 pB = __float22bfloat162_rn(
                make_float2(acc[nt][2] + bB, acc[nt][3] + bB));
            *(__nv_bfloat162*)&sPb[oA * LDS1 + w] = pA;
            *(__nv_bfloat162*)&sPb[oB * LDS1 + w] = pB;
        }
    }
    __syncthreads();

    {   // coalesced x_proj write-out (2048 uint4, 4/thread)
        __nv_bfloat16* xp = g_xp + (b * 128 + h) * 16384;
#pragma unroll
        for (int i = 0; i < 4; i++) {
            int idx = t + i * 512;
            int o = idx >> 4, c8 = (idx & 15) * 8;
            *(uint4*)&xp[o * 128 + c8] = *(const uint4*)&sPb[o * LDS1 + c8];
        }
    }
}

// ---- K2: per-(b,o) plane: concurrent h-scan + v-scan, merge, store ----
__global__ __launch_bounds__(256) void k2(const float* __restrict__ A,
                                          const float* __restrict__ Bvec) {
    extern __shared__ __align__(16) char smch[];
    __nv_bfloat16* sX = (__nv_bfloat16*)smch;
    __nv_bfloat16* sH = (__nv_bfloat16*)(smch + 34816);
    __nv_bfloat16* sV = (__nv_bfloat16*)(smch + 69632);

    const int t = threadIdx.x;
    const int o = blockIdx.x, b = blockIdx.y;
    const float a = tanhf(__ldg(&A[o]));
    const float bv = __ldg(&Bvec[o]);
    const int gbase = b * 2097152 + o * 128;   // + h*16384 + w

    {   // async load plane (2048 x 16B)
        const __nv_bfloat16* src = g_xp + gbase;
        const uint32_t sX_u = smem_u32(sX);
#pragma unroll
        for (int i = 0; i < 8; i++) {
            int idx = t + i * 256;
            int h = idx >> 4, c8 = (idx & 15) * 8;
            CP_ASYNC16(sX_u + (uint32_t)((h * LDK2 + c8) * 2), &src[h * 16384 + c8]);
        }
        CP_COMMIT(); CP_WAIT0();
    }
    __syncthreads();

    if (t < 128) {   // warps 0-3: h-scan row t -> sH
        const __nv_bfloat16* xr = &sX[t * LDK2];
        __nv_bfloat16* hr = &sH[t * LDK2];
        float st = 0.0f;
#pragma unroll 4
        for (int wb = 0; wb < 32; wb++) {
            uint2 u = *(const uint2*)&xr[wb * 4];
            float2 f0 = __bfloat1622float2(*(__nv_bfloat162*)&u.x);
            float2 f1 = __bfloat1622float2(*(__nv_bfloat162*)&u.y);
            st = fmaf(a, st, bv * f0.x); f0.x = st;
            st = fmaf(a, st, bv * f0.y); f0.y = st;
            st = fmaf(a, st, bv * f1.x); f1.x = st;
            st = fmaf(a, st, bv * f1.y); f1.y = st;
            __nv_bfloat162 p0 = __float22bfloat162_rn(f0);
            __nv_bfloat162 p1 = __float22bfloat162_rn(f1);
            *(uint2*)&hr[wb * 4] = make_uint2(*(uint32_t*)&p0, *(uint32_t*)&p1);
        }
    } else {         // warps 4-7: v-scan column w = t-128 -> sV
        const int w = t - 128;
        float st = 0.0f;
#pragma unroll 4
        for (int h = 0; h < 128; h++) {
            float xvv = __bfloat162float(sX[h * LDK2 + w]);
            st = fmaf(a, st, bv * xvv);
            sV[h * LDK2 + w] = __float2bfloat16(st);
        }
    }
    __syncthreads();

    {   // merge + store h_sum plane (2048 uint4)
        __nv_bfloat16* dst = g_hs + gbase;
#pragma unroll
        for (int i = 0; i < 8; i++) {
            int idx = t + i * 256;
            int h = idx >> 4, c8 = (idx & 15) * 8;
            uint4 uh = *(const uint4*)&sH[h * LDK2 + c8];
            uint4 uv = *(const uint4*)&sV[h * LDK2 + c8];
            uint4 r;
            *(__nv_bfloat162*)&r.x = __hadd2(*(__nv_bfloat162*)&uh.x, *(__nv_bfloat162*)&uv.x);
            *(__nv_bfloat162*)&r.y = __hadd2(*(__nv_bfloat162*)&uh.y, *(__nv_bfloat162*)&uv.y);
            *(__nv_bfloat162*)&r.z = __hadd2(*(__nv_bfloat162*)&uh.z, *(__nv_bfloat162*)&uv.z);
            *(__nv_bfloat162*)&r.w = __hadd2(*(__nv_bfloat162*)&uh.w, *(__nv_bfloat162*)&uv.w);
            *(uint4*)&dst[h * 16384 + c8] = r;
        }
    }
}

// ---- K3: per-(b,h): out = h_sum @ Wout^T (HMMA), m=c n=w, fused epilogue ----
// smem: sHs bf16 [o][w] 34816B @0 ; sWo bf16 [c][o] 17408B @34816
//       sR fp32 [c][w] 33792B overlays sHs after MMA.
__global__ __launch_bounds__(256) void k3(
    const float* __restrict__ x, const float* __restrict__ prior,
    const float* __restrict__ Wout, const float* __restrict__ b_out,
    const float* __restrict__ alpha_p, const float* __restrict__ gamma_p,
    float* __restrict__ out)
{
    extern __shared__ __align__(16) char smch[];
    __nv_bfloat16* sHs = (__nv_bfloat16*)smch;
    __nv_bfloat16* sWo = (__nv_bfloat16*)(smch + 34816);
    float* sR = (float*)smch;
    __shared__ float s_pr[128], s_bo[64];

    const int t = threadIdx.x;
    const int wid = t >> 5, lid = t & 31;
    const int h = blockIdx.x, b = blockIdx.y;
    const float alpha = __ldg(alpha_p), gamma = __ldg(gamma_p);

    {   // async-stage sHs <- h_sum [o][w] (2048 x 16B)
        const __nv_bfloat16* hs = g_hs + (b * 128 + h) * 16384;
        const uint32_t sHs_u = smem_u32(sHs);
#pragma unroll
        for (int i = 0; i < 8; i++) {
            int idx = t + i * 256;
            int o = idx >> 4, w8 = (idx & 15) * 8;
            CP_ASYNC16(sHs_u + (uint32_t)((o * LDA3 + w8) * 2), &hs[o * 128 + w8]);
        }
        CP_COMMIT();
    }

    if (t < 128) s_pr[t] = prior_at(prior, b, h, t);
    if (t < 64) s_bo[t] = b_out[t];

    // ---- prefetch epilogue x reads (8 x LDG.128) ----
    const int base_bh = b * 1048576 + h * 128;
    float4 xv[8];
#pragma unroll
    for (int i = 0; i < 8; i++) {
        int idx = t + i * 256;               // 2048 = 64c x 32 w4
        int c = idx >> 5, w4 = (idx & 31) * 4;
        xv[i] = *(const float4*)&x[base_bh + c * 16384 + w4];
    }

    {   // sWo <- Wout fp32 -> bf16 (LDG.128 + STS.64, 8/thread)
#pragma unroll
        for (int i = 0; i < 8; i++) {
            int idx = t + i * 256;           // 2048 = 64c x 32 o4-groups
            int c = idx >> 5, o4 = (idx & 31) * 4;
            float4 wv = *(const float4*)&Wout[c * 128 + o4];
            __nv_bfloat162 p0 = __float22bfloat162_rn(make_float2(wv.x, wv.y));
            __nv_bfloat162 p1 = __float22bfloat162_rn(make_float2(wv.z, wv.w));
            *(uint2*)&sWo[c * LDB3 + o4] = make_uint2(*(uint32_t*)&p0, *(uint32_t*)&p1);
        }
    }
    CP_WAIT0();
    __syncthreads();

    // MMA: m=c (8 warps = 4 m-tiles x 2 w-halves), n=w, K=128
    const int c0 = (wid & 3) * 16;
    const int nh = wid >> 2;
    float acc[8][4];
#pragma unroll
    for (int nt = 0; nt < 8; nt++)
#pragma unroll
        for (int j = 0; j < 4; j++) acc[nt][j] = 0.f;

    const uint32_t sHs_u = smem_u32(sHs), sWo_u = smem_u32(sWo);
    const uint32_t a_base = sWo_u +
        (uint32_t)(((c0 + (lid & 15)) * LDB3 + ((lid >> 4) << 3)) * 2);
    const int b_row = (lid & 7) + (((lid >> 3) & 1) << 3);
    const int b_col = nh * 64 + ((lid >> 4) << 3);
    const uint32_t b_base = sHs_u + (uint32_t)((b_row * LDA3 + b_col) * 2);

#pragma unroll
    for (int ks = 0; ks < 8; ks++) {
        uint32_t afr[4];
        ldsm_x4(afr, a_base + (uint32_t)(ks * 16 * 2));
#pragma unroll
        for (int nt16 = 0; nt16 < 4; nt16++) {
            uint32_t bfr[4];
            ldsm_x4_trans(bfr, b_base + (uint32_t)((ks * 16 * LDA3 + nt16 * 16) * 2));
            mma_bf16(acc[2 * nt16],     afr, bfr);
            mma_bf16(acc[2 * nt16 + 1], afr, bfr + 2);
        }
    }
    __syncthreads();   // overlay sR

    {   // acc -> sR[c][w], w-contiguous float2 (16 STS.64/thread)
        const int g = lid >> 2, q2 = (lid & 3) * 2;
        const int cA = c0 + g, cB = c0 + g + 8;
#pragma unroll
        for (int nt = 0; nt < 8; nt++) {
            int w = nh * 64 + nt * 8 + q2;
            *(float2*)&sR[cA * LDP + w] = make_float2(acc[nt][0], acc[nt][1]);
            *(float2*)&sR[cB * LDP + w] = make_float2(acc[nt][2], acc[nt][3]);
        }
    }
    __syncthreads();

    {   // fused epilogue, float4: out = x + alpha*pr + gamma*(res + b_out)
#pragma unroll
        for (int i = 0; i < 8; i++) {
            int idx = t + i * 256;           // 2048 = 64c x 32 w4
            int c = idx >> 5, w4 = (idx & 31) * 4;
            int gb = base_bh + c * 16384 + w4;
            float4 rv = *(const float4*)&sR[c * LDP + w4];
            float4 pv = *(const float4*)&s_pr[w4];
            float bo = s_bo[c];
            float4 r;
            r.x = fmaf(alpha, pv.x, xv[i].x) + gamma * (rv.x + bo);
            r.y = fmaf(alpha, pv.y, xv[i].y) + gamma * (rv.y + bo);
            r.z = fmaf(alpha, pv.z, xv[i].z) + gamma * (rv.z + bo);
            r.w = fmaf(alpha, pv.w, xv[i].w) + gamma * (rv.w + bo);
            *(float4*)&out[gb] = r;
        }
    }
}

extern "C" void kernel_launch(void* const* d_in, const int* in_sizes, int n_in,
                              void* d_out, int out_size) {
    const float* x      = (const float*)d_in[0];
    const float* prior  = (const float*)d_in[1];
    const float* W_in   = (const float*)d_in[2];
    const float* b_in   = (const float*)d_in[3];
    const float* A      = (const float*)d_in[4];
    const float* B      = (const float*)d_in[5];
    const float* alpha  = (const float*)d_in[6];
    const float* gamma  = (const float*)d_in[7];
    const float* W_out  = (const float*)d_in[8];
    const float* b_out  = (const float*)d_in[9];
    float* out = (float*)d_out;

    const int smem_k1 = 68608;
    const int smem_k2 = 104448;
    const int smem_k3 = 34816 + 17408;   // 52224

    cudaFuncSetAttribute(k1, cudaFuncAttributeMaxDynamicSharedMemorySize, smem_k1);
    cudaFuncSetAttribute(k2, cudaFuncAttributeMaxDynamicSharedMemorySize, smem_k2);
    cudaFuncSetAttribute(k3, cudaFuncAttributeMaxDynamicSharedMemorySize, smem_k3);

    dim3 grid(HDIM, BSZ);
    k1<<<grid, 512, smem_k1>>>(x, prior, W_in, b_in, alpha);
    k2<<<grid, 256, smem_k2>>>(A, B);
    k3<<<grid, 256, smem_k3>>>(x, prior, W_out, b_out, alpha, gamma, out);
}

// round 15
// speedup vs baseline: 1.5444x; 1.0125x over previous
#include <cuda_runtime.h>
#include <cuda_bf16.h>
#include <cstdint>

#define NBLK 296
#define NTILE 1024

// smem strides (bf16 elems)
#define LDA1 136   // P1 F_mod: [c][w]
#define LDB1 72    // P1 Win:   [o][c]
#define LDS1 136   // P1 staging [o][w]
#define LDA3 136   // P3 h_sum: [o][w]
#define LDB3 136   // P3 Wout:  [c][o]
#define LDP  132   // P3 fp32 staging [c][w]
#define LDK2 136   // P2 planes [h][w]

// phase smem offsets (bytes); dyn smem = 104448
#define P1_SW 0
#define P1_XF 18432
#define P1_F  51200
#define P1_PB 68608
#define P2_X  0
#define P2_H  34816
#define P2_V  69632
#define P3_WO 0
#define P3_HS 17408
#define P3_R  17408

// ---- scratch (device globals; allocation-free) ----
__device__ __nv_bfloat16 g_xp[8*128*128*128];  // x_proj [b][h][o][w]
__device__ __nv_bfloat16 g_hs[8*128*128*128];  // h_sum  [b][h][o][w]
__device__ int g_bar[2];

__device__ __forceinline__ uint32_t smem_u32(const void* p) {
    return (uint32_t)__cvta_generic_to_shared(p);
}

#define CP_ASYNC16(dst, src) \
    asm volatile("cp.async.cg.shared.global [%0], [%1], 16;" \
                 :: "r"(dst), "l"(src) : "memory")
#define CP_COMMIT() asm volatile("cp.async.commit_group;" ::: "memory")
#define CP_WAIT0()  asm volatile("cp.async.wait_group 0;" ::: "memory")

__device__ __forceinline__ void ldsm_x4_trans(uint32_t* r, uint32_t a) {
    asm volatile("ldmatrix.sync.aligned.m8n8.x4.trans.shared.b16 {%0,%1,%2,%3}, [%4];"
        : "=r"(r[0]), "=r"(r[1]), "=r"(r[2]), "=r"(r[3]) : "r"(a));
}
__device__ __forceinline__ void ldsm_x4(uint32_t* r, uint32_t a) {
    asm volatile("ldmatrix.sync.aligned.m8n8.x4.shared.b16 {%0,%1,%2,%3}, [%4];"
        : "=r"(r[0]), "=r"(r[1]), "=r"(r[2]), "=r"(r[3]) : "r"(a));
}
__device__ __forceinline__ void mma_bf16(float* d, const uint32_t* a, const uint32_t* b) {
    asm volatile("mma.sync.aligned.m16n8k16.row.col.f32.bf16.bf16.f32 "
        "{%0,%1,%2,%3}, {%4,%5,%6,%7}, {%8,%9}, {%0,%1,%2,%3};"
        : "+f"(d[0]), "+f"(d[1]), "+f"(d[2]), "+f"(d[3])
        : "r"(a[0]), "r"(a[1]), "r"(a[2]), "r"(a[3]), "r"(b[0]), "r"(b[1]));
}

__device__ __forceinline__ float prior_at(const float* __restrict__ prior,
                                          int b, int h, int w) {
    const float s = 31.0f / 127.0f;
    float ys = h * s, xs = w * s;
    int y0 = (int)ys, x0 = (int)xs;
    int y1 = min(y0 + 1, 31), x1 = min(x0 + 1, 31);
    float wy = ys - (float)y0, wx = xs - (float)x0;
    const float* p = prior + b * 1024;
    float p00 = p[y0*32+x0], p01 = p[y0*32+x1];
    float p10 = p[y1*32+x0], p11 = p[y1*32+x1];
    float top = p00 + (p01 - p00) * wx;
    float bot = p10 + (p11 - p10) * wx;
    float v = top + (bot - top) * wy;
    return fminf(1.0f, fmaxf(-1.0f, v));
}

// global barrier: all NBLK blocks resident by construction (launch_bounds(512,2))
__device__ __forceinline__ void gbarrier(int idx) {
    __syncthreads();
    if (threadIdx.x == 0) {
        __threadfence();
        atomicAdd(&g_bar[idx], 1);
        volatile int* vc = &g_bar[idx];
        while (*vc < NBLK) { }
    }
    __syncthreads();
}

__global__ __launch_bounds__(512, 2) void kfused(
    const float* __restrict__ x, const float* __restrict__ prior,
    const float* __restrict__ Win, const float* __restrict__ b_in,
    const float* __restrict__ A, const float* __restrict__ Bvec,
    const float* __restrict__ alpha_p, const float* __restrict__ gamma_p,
    const float* __restrict__ Wout, const float* __restrict__ b_out,
    float* __restrict__ out)
{
    extern __shared__ __align__(16) char smch[];
    __shared__ float s_pr[128], s_bin[128], s_bo[64];

    const int t = threadIdx.x;
    const int wid = t >> 5, lid = t & 31;
    const int bid = blockIdx.x;
    const float alpha = __ldg(alpha_p), gamma = __ldg(gamma_p);

    // ================= PHASE 1: x_proj = F_mod @ Win^T + b_in =================
    {
        __nv_bfloat16* sW  = (__nv_bfloat16*)(smch + P1_SW);
        float*         sXf = (float*)(smch + P1_XF);
        __nv_bfloat16* sF  = (__nv_bfloat16*)(smch + P1_F);
        __nv_bfloat16* sPb = (__nv_bfloat16*)(smch + P1_PB);

        // stage Win once per block (fp32 -> bf16, padded [o][c])
#pragma unroll
        for (int i = 0; i < 4; i++) {
            int idx = t + i * 512;           // 2048 = 128o x 16 c4
            int o = idx >> 4, c4 = (idx & 15) * 4;
            float4 wv = *(const float4*)&Win[o * 64 + c4];
            __nv_bfloat162 p0 = __float22bfloat162_rn(make_float2(wv.x, wv.y));
            __nv_bfloat162 p1 = __float22bfloat162_rn(make_float2(wv.z, wv.w));
            *(uint2*)&sW[o * LDB1 + c4] = make_uint2(*(uint32_t*)&p0, *(uint32_t*)&p1);
        }
        if (t < 128) s_bin[t] = b_in[t];
        __syncthreads();

        for (int tile = bid; tile < NTILE; tile += NBLK) {
            const int b = tile >> 7, h = tile & 127;

            {   // cp.async x row (32KB) into sXf
                const float* xrow = x + b * 1048576 + h * 128;
                const uint32_t sXf_u = smem_u32(sXf);
#pragma unroll
                for (int i = 0; i < 4; i++) {
                    int idx = t + i * 512;   // 2048 = 64c x 32 chunks
                    int c = idx >> 5, ch = (idx & 31) * 4;
                    CP_ASYNC16(sXf_u + (uint32_t)(idx * 16), &xrow[c * 16384 + ch]);
                }
                CP_COMMIT();
            }
            if (t < 128) s_pr[t] = prior_at(prior, b, h, t);
            CP_WAIT0();
            __syncthreads();

            {   // sF <- F_mod bf16 [c][w]
#pragma unroll
                for (int i = 0; i < 4; i++) {
                    int idx = t + i * 512;   // 2048 = 64c x 32 w4
                    int c = idx >> 5, w4 = (idx & 31) * 4;
                    float4 f = *(const float4*)&sXf[c * 128 + w4];
                    float4 pv = *(const float4*)&s_pr[w4];
                    f.x += alpha * pv.x; f.y += alpha * pv.y;
                    f.z += alpha * pv.z; f.w += alpha * pv.w;
                    __nv_bfloat162 p0 = __float22bfloat162_rn(make_float2(f.x, f.y));
                    __nv_bfloat162 p1 = __float22bfloat162_rn(make_float2(f.z, f.w));
                    *(uint2*)&sF[c * LDA1 + w4] = make_uint2(*(uint32_t*)&p0, *(uint32_t*)&p1);
                }
            }
            __syncthreads();

            // MMA: m=o (16 warps = 8 m-tiles x 2 w-halves), n=w, K=64
            const int o0 = (wid & 7) * 16;
            const int nh = wid >> 3;
            float acc[8][4];
#pragma unroll
            for (int nt = 0; nt < 8; nt++)
#pragma unroll
                for (int j = 0; j < 4; j++) acc[nt][j] = 0.f;

            const uint32_t sF_u = smem_u32(sF), sW_u = smem_u32(sW);
            const uint32_t a_base = sW_u +
                (uint32_t)(((o0 + (lid & 15)) * LDB1 + ((lid >> 4) << 3)) * 2);
            const int b_row = (lid & 7) + (((lid >> 3) & 1) << 3);
            const int b_col = nh * 64 + ((lid >> 4) << 3);
            const uint32_t b_base = sF_u + (uint32_t)((b_row * LDA1 + b_col) * 2);

#pragma unroll
            for (int ks = 0; ks < 4; ks++) {
                uint32_t afr[4];
                ldsm_x4(afr, a_base + (uint32_t)(ks * 16 * 2));
#pragma unroll
                for (int nt16 = 0; nt16 < 4; nt16++) {
                    uint32_t bfr[4];
                    ldsm_x4_trans(bfr, b_base + (uint32_t)((ks * 16 * LDA1 + nt16 * 16) * 2));
                    mma_bf16(acc[2 * nt16],     afr, bfr);
                    mma_bf16(acc[2 * nt16 + 1], afr, bfr + 2);
                }
            }
            __syncthreads();

            {   // acc (+bias) -> sPb[o][w], w-contiguous bf162
                const int g = lid >> 2, q2 = (lid & 3) * 2;
                const int oA = o0 + g, oB = o0 + g + 8;
                const float bA = s_bin[oA], bB = s_bin[oB];
#pragma unroll
                for (int nt = 0; nt < 8; nt++) {
                    int w = nh * 64 + nt * 8 + q2;
                    __nv_bfloat162 pA = __float22bfloat162_rn(
                        make_float2(acc[nt][0] + bA, acc[nt][1] + bA));
                    __nv_bfloat162 pB = __float22bfloat162_rn(
                        make_float2(acc[nt][2] + bB, acc[nt][3] + bB));
                    *(__nv_bfloat162*)&sPb[oA * LDS1 + w] = pA;
                    *(__nv_bfloat162*)&sPb[oB * LDS1 + w] = pB;
                }
            }
            __syncthreads();

            {   // coalesced x_proj write-out
                __nv_bfloat16* xp = g_xp + (b * 128 + h) * 16384;
#pragma unroll
                for (int i = 0; i < 4; i++) {
                    int idx = t + i * 512;
                    int o = idx >> 4, c8 = (idx & 15) * 8;
                    *(uint4*)&xp[o * 128 + c8] = *(const uint4*)&sPb[o * LDS1 + c8];
                }
            }
            __syncthreads();
        }
    }

    gbarrier(0);

    // ================= PHASE 2: dual scan per (b,o) plane =================
    {
        __nv_bfloat16* sX = (__nv_bfloat16*)(smch + P2_X);
        __nv_bfloat16* sH = (__nv_bfloat16*)(smch + P2_H);
        __nv_bfloat16* sV = (__nv_bfloat16*)(smch + P2_V);

        for (int pl = bid; pl < NTILE; pl += NBLK) {
            const int b = pl >> 7, o = pl & 127;
            const float a = tanhf(__ldg(&A[o]));
            const float bv = __ldg(&Bvec[o]);
            const int gbase = b * 2097152 + o * 128;

            {   // async load plane
                const __nv_bfloat16* src = g_xp + gbase;
                const uint32_t sX_u = smem_u32(sX);
#pragma unroll
                for (int i = 0; i < 4; i++) {
                    int idx = t + i * 512;
                    int h = idx >> 4, c8 = (idx & 15) * 8;
                    CP_ASYNC16(sX_u + (uint32_t)((h * LDK2 + c8) * 2),
                               &src[h * 16384 + c8]);
                }
                CP_COMMIT(); CP_WAIT0();
            }
            __syncthreads();

            if (t < 128) {   // h-scan row t -> sH
                const __nv_bfloat16* xr = &sX[t * LDK2];
                __nv_bfloat16* hr = &sH[t * LDK2];
                float st = 0.0f;
#pragma unroll 4
                for (int wb = 0; wb < 32; wb++) {
                    uint2 u = *(const uint2*)&xr[wb * 4];
                    float2 f0 = __bfloat1622float2(*(__nv_bfloat162*)&u.x);
                    float2 f1 = __bfloat1622float2(*(__nv_bfloat162*)&u.y);
                    st = fmaf(a, st, bv * f0.x); f0.x = st;
                    st = fmaf(a, st, bv * f0.y); f0.y = st;
                    st = fmaf(a, st, bv * f1.x); f1.x = st;
                    st = fmaf(a, st, bv * f1.y); f1.y = st;
                    __nv_bfloat162 p0 = __float22bfloat162_rn(f0);
                    __nv_bfloat162 p1 = __float22bfloat162_rn(f1);
                    *(uint2*)&hr[wb * 4] = make_uint2(*(uint32_t*)&p0, *(uint32_t*)&p1);
                }
            } else if (t < 256) {  // v-scan column w = t-128 -> sV
                const int w = t - 128;
                float st = 0.0f;
#pragma unroll 4
                for (int h = 0; h < 128; h++) {
                    float xvv = __bfloat162float(sX[h * LDK2 + w]);
                    st = fmaf(a, st, bv * xvv);
                    sV[h * LDK2 + w] = __float2bfloat16(st);
                }
            }
            __syncthreads();

            {   // merge + store h_sum plane
                __nv_bfloat16* dst = g_hs + gbase;
#pragma unroll
                for (int i = 0; i < 4; i++) {
                    int idx = t + i * 512;
                    int h = idx >> 4, c8 = (idx & 15) * 8;
                    uint4 uh = *(const uint4*)&sH[h * LDK2 + c8];
                    uint4 uv = *(const uint4*)&sV[h * LDK2 + c8];
                    uint4 r;
                    *(__nv_bfloat162*)&r.x = __hadd2(*(__nv_bfloat162*)&uh.x, *(__nv_bfloat162*)&uv.x);
                    *(__nv_bfloat162*)&r.y = __hadd2(*(__nv_bfloat162*)&uh.y, *(__nv_bfloat162*)&uv.y);
                    *(__nv_bfloat162*)&r.z = __hadd2(*(__nv_bfloat162*)&uh.z, *(__nv_bfloat162*)&uv.z);
                    *(__nv_bfloat162*)&r.w = __hadd2(*(__nv_bfloat162*)&uh.w, *(__nv_bfloat162*)&uv.w);
                    *(uint4*)&dst[h * 16384 + c8] = r;
                }
            }
            __syncthreads();
        }
    }

    gbarrier(1);

    // ================= PHASE 3: out = x + a*pr + g*(h_sum @ Wout^T + b) ======
    {
        __nv_bfloat16* sWo = (__nv_bfloat16*)(smch + P3_WO);
        __nv_bfloat16* sHs = (__nv_bfloat16*)(smch + P3_HS);
        float* sR = (float*)(smch + P3_R);

        // stage Wout once per block (fp32 -> bf16, padded [c][o])
#pragma unroll
        for (int i = 0; i < 4; i++) {
            int idx = t + i * 512;           // 2048 = 64c x 32 o4
            int c = idx >> 5, o4 = (idx & 31) * 4;
            float4 wv = *(const float4*)&Wout[c * 128 + o4];
            __nv_bfloat162 p0 = __float22bfloat162_rn(make_float2(wv.x, wv.y));
            __nv_bfloat162 p1 = __float22bfloat162_rn(make_float2(wv.z, wv.w));
            *(uint2*)&sWo[c * LDB3 + o4] = make_uint2(*(uint32_t*)&p0, *(uint32_t*)&p1);
        }
        if (t < 64) s_bo[t] = b_out[t];
        __syncthreads();

        for (int tile = bid; tile < NTILE; tile += NBLK) {
            const int b = tile >> 7, h = tile & 127;
            const int base_bh = b * 1048576 + h * 128;

            {   // cp.async sHs <- h_sum [o][w]
                const __nv_bfloat16* hs = g_hs + (b * 128 + h) * 16384;
                const uint32_t sHs_u = smem_u32(sHs);
#pragma unroll
                for (int i = 0; i < 4; i++) {
                    int idx = t + i * 512;
                    int o = idx >> 4, w8 = (idx & 15) * 8;
                    CP_ASYNC16(sHs_u + (uint32_t)((o * LDA3 + w8) * 2),
                               &hs[o * 128 + w8]);
                }
                CP_COMMIT();
            }
            if (t < 128) s_pr[t] = prior_at(prior, b, h, t);

            // prefetch epilogue x reads
            float4 xv[4];
#pragma unroll
            for (int i = 0; i < 4; i++) {
                int idx = t + i * 512;       // 2048 = 64c x 32 w4
                int c = idx >> 5, w4 = (idx & 31) * 4;
                xv[i] = *(const float4*)&x[base_bh + c * 16384 + w4];
            }
            CP_WAIT0();
            __syncthreads();

            // MMA: m=c (16 warps = 4 m-tiles x 4 w-quarters), n=w, K=128
            const int c0 = (wid & 3) * 16;
            const int q = wid >> 2;
            float acc[4][4];
#pragma unroll
            for (int nt = 0; nt < 4; nt++)
#pragma unroll
                for (int j = 0; j < 4; j++) acc[nt][j] = 0.f;

            const uint32_t sHs_u = smem_u32(sHs), sWo_u = smem_u32(sWo);
            const uint32_t a_base = sWo_u +
                (uint32_t)(((c0 + (lid & 15)) * LDB3 + ((lid >> 4) << 3)) * 2);
            const int b_row = (lid & 7) + (((lid >> 3) & 1) << 3);
            const int b_col = q * 32 + ((lid >> 4) << 3);
            const uint32_t b_base = sHs_u + (uint32_t)((b_row * LDA3 + b_col) * 2);

#pragma unroll
            for (int ks = 0; ks < 8; ks++) {
                uint32_t afr[4];
                ldsm_x4(afr, a_base + (uint32_t)(ks * 16 * 2));
#pragma unroll
                for (int nt16 = 0; nt16 < 2; nt16++) {
                    uint32_t bfr[4];
                    ldsm_x4_trans(bfr, b_base + (uint32_t)((ks * 16 * LDA3 + nt16 * 16) * 2));
                    mma_bf16(acc[2 * nt16],     afr, bfr);
                    mma_bf16(acc[2 * nt16 + 1], afr, bfr + 2);
                }
            }
            __syncthreads();   // overlay sR on sHs

            {   // acc -> sR[c][w], w-contiguous float2
                const int g = lid >> 2, q2 = (lid & 3) * 2;
                const int cA = c0 + g, cB = c0 + g + 8;
#pragma unroll
                for (int nt = 0; nt < 4; nt++) {
                    int w = q * 32 + nt * 8 + q2;
                    *(float2*)&sR[cA * LDP + w] = make_float2(acc[nt][0], acc[nt][1]);
                    *(float2*)&sR[cB * LDP + w] = make_float2(acc[nt][2], acc[nt][3]);
                }
            }
            __syncthreads();

            {   // fused epilogue
#pragma unroll
                for (int i = 0; i < 4; i++) {
                    int idx = t + i * 512;
                    int c = idx >> 5, w4 = (idx & 31) * 4;
                    int gb = base_bh + c * 16384 + w4;
                    float4 rv = *(const float4*)&sR[c * LDP + w4];
                    float4 pv = *(const float4*)&s_pr[w4];
                    float bo = s_bo[c];
                    float4 r;
                    r.x = fmaf(alpha, pv.x, xv[i].x) + gamma * (rv.x + bo);
                    r.y = fmaf(alpha, pv.y, xv[i].y) + gamma * (rv.y + bo);
                    r.z = fmaf(alpha, pv.z, xv[i].z) + gamma * (rv.z + bo);
                    r.w = fmaf(alpha, pv.w, xv[i].w) + gamma * (rv.w + bo);
                    *(float4*)&out[gb] = r;
                }
            }
            __syncthreads();
        }
    }
}

extern "C" void kernel_launch(void* const* d_in, const int* in_sizes, int n_in,
                              void* d_out, int out_size) {
    const float* x      = (const float*)d_in[0];
    const float* prior  = (const float*)d_in[1];
    const float* W_in   = (const float*)d_in[2];
    const float* b_in   = (const float*)d_in[3];
    const float* A      = (const float*)d_in[4];
    const float* B      = (const float*)d_in[5];
    const float* alpha  = (const float*)d_in[6];
    const float* gamma  = (const float*)d_in[7];
    const float* W_out  = (const float*)d_in[8];
    const float* b_out  = (const float*)d_in[9];
    float* out = (float*)d_out;

    void* bar_addr = nullptr;
    cudaGetSymbolAddress(&bar_addr, g_bar);
    cudaMemsetAsync(bar_addr, 0, 2 * sizeof(int));

    const int smem = 104448;
    cudaFuncSetAttribute(kfused, cudaFuncAttributeMaxDynamicSharedMemorySize, smem);
    kfused<<<NBLK, 512, smem>>>(x, prior, W_in, b_in, A, B,
                                alpha, gamma, W_out, b_out, out);
}